// round 1
// baseline (speedup 1.0000x reference)
#include <cuda_runtime.h>
#include <cuda_bf16.h>
#include <math.h>

// Problem constants
#define BB   2
#define TT   2048
#define DD   1024
#define HH   16
#define DHH  64
#define FFD  4096
#define ROWS (BB*TT)          // 4096 token rows
#define EPSF 1e-5f

// ---------------------------------------------------------------------------
// Scratch: one big __device__ global (no allocations allowed).
// layout: h(4M) q(4M) k(4M) v(4M) att(4M) ff(16M) floats
// ---------------------------------------------------------------------------
#define SEG (ROWS * DD)                    // 4194304
__device__ float g_scratch[5 * SEG + ROWS * FFD];

// ---------------------------------------------------------------------------
// LayerNorm: one block per row, 256 threads, 4 elems/thread (D=1024)
// ---------------------------------------------------------------------------
__global__ __launch_bounds__(256) void ln_kernel(
    const float* __restrict__ x, const float* __restrict__ g,
    const float* __restrict__ b, float* __restrict__ o)
{
    const int row = blockIdx.x;
    const int tid = threadIdx.x;
    const float* xr = x + (long long)row * DD;

    float4 v = *(const float4*)(xr + tid * 4);
    float s  = v.x + v.y + v.z + v.w;
    float ss = v.x * v.x + v.y * v.y + v.z * v.z + v.w * v.w;

    // warp reduce
    #pragma unroll
    for (int off = 16; off > 0; off >>= 1) {
        s  += __shfl_xor_sync(0xffffffff, s,  off);
        ss += __shfl_xor_sync(0xffffffff, ss, off);
    }
    __shared__ float sbuf[8], ssbuf[8];
    const int warp = tid >> 5, lane = tid & 31;
    if (lane == 0) { sbuf[warp] = s; ssbuf[warp] = ss; }
    __syncthreads();
    float S = 0.f, SS = 0.f;
    #pragma unroll
    for (int i = 0; i < 8; i++) { S += sbuf[i]; SS += ssbuf[i]; }

    const float mu  = S * (1.0f / DD);
    const float var = SS * (1.0f / DD) - mu * mu;
    const float rs  = rsqrtf(var + EPSF);

    float4 gg = *(const float4*)(g + tid * 4);
    float4 bb = *(const float4*)(b + tid * 4);
    float4 out;
    out.x = (v.x - mu) * rs * gg.x + bb.x;
    out.y = (v.y - mu) * rs * gg.y + bb.y;
    out.z = (v.z - mu) * rs * gg.z + bb.z;
    out.w = (v.w - mu) * rs * gg.w + bb.w;
    *(float4*)(o + (long long)row * DD + tid * 4) = out;
}

// ---------------------------------------------------------------------------
// SGEMM: C[M,N] = A[M,K] @ W[N,K]^T  (both K-contiguous row-major)
// 128x128 tile, BK=16, 256 threads, 8x8 per-thread microtile.
// EPI: 0 = none, 1 = C = acc + R, 2 = C = gelu(acc), 3 = C += acc
// ---------------------------------------------------------------------------
#define GBK 16

template<int EPI>
__global__ __launch_bounds__(256) void gemm_tn(
    const float* __restrict__ A, const float* __restrict__ W,
    float* __restrict__ C, const float* __restrict__ R,
    int M, int N, int K)
{
    __shared__ float As[GBK][128];
    __shared__ float Ws[GBK][128];

    const int bm  = blockIdx.y * 128;
    const int bn  = blockIdx.x * 128;
    const int tid = threadIdx.x;
    const int ty  = tid >> 4;   // 0..15 -> row group
    const int tx  = tid & 15;   // 0..15 -> col group

    float acc[8][8];
    #pragma unroll
    for (int r = 0; r < 8; r++)
        #pragma unroll
        for (int c = 0; c < 8; c++) acc[r][c] = 0.f;

    const float* Ab = A + (long long)bm * K;
    const float* Wb = W + (long long)bn * K;

    for (int k0 = 0; k0 < K; k0 += GBK) {
        #pragma unroll
        for (int i = 0; i < 2; i++) {
            const int lin = tid + i * 256;
            const int row = lin >> 2;
            const int kq  = (lin & 3) << 2;
            float4 a4 = *(const float4*)(Ab + (long long)row * K + k0 + kq);
            As[kq + 0][row] = a4.x; As[kq + 1][row] = a4.y;
            As[kq + 2][row] = a4.z; As[kq + 3][row] = a4.w;
            float4 w4 = *(const float4*)(Wb + (long long)row * K + k0 + kq);
            Ws[kq + 0][row] = w4.x; Ws[kq + 1][row] = w4.y;
            Ws[kq + 2][row] = w4.z; Ws[kq + 3][row] = w4.w;
        }
        __syncthreads();

        #pragma unroll
        for (int kk = 0; kk < GBK; kk++) {
            float a[8], bb[8];
            *(float4*)&a[0]  = *(const float4*)&As[kk][ty * 8];
            *(float4*)&a[4]  = *(const float4*)&As[kk][ty * 8 + 4];
            *(float4*)&bb[0] = *(const float4*)&Ws[kk][tx * 8];
            *(float4*)&bb[4] = *(const float4*)&Ws[kk][tx * 8 + 4];
            #pragma unroll
            for (int r = 0; r < 8; r++)
                #pragma unroll
                for (int c = 0; c < 8; c++)
                    acc[r][c] += a[r] * bb[c];
        }
        __syncthreads();
    }

    // epilogue
    #pragma unroll
    for (int r = 0; r < 8; r++) {
        const int row = bm + ty * 8 + r;
        float* crow = C + (long long)row * N + bn + tx * 8;
        const float* rrow = (EPI == 1) ? (R + (long long)row * N + bn + tx * 8) : nullptr;
        #pragma unroll
        for (int cq = 0; cq < 2; cq++) {
            float4 o;
            float v0 = acc[r][cq * 4 + 0], v1 = acc[r][cq * 4 + 1];
            float v2 = acc[r][cq * 4 + 2], v3 = acc[r][cq * 4 + 3];
            if (EPI == 1) {
                float4 rr = *(const float4*)(rrow + cq * 4);
                v0 += rr.x; v1 += rr.y; v2 += rr.z; v3 += rr.w;
            } else if (EPI == 2) {
                v0 = 0.5f * v0 * (1.0f + erff(v0 * 0.70710678118654752f));
                v1 = 0.5f * v1 * (1.0f + erff(v1 * 0.70710678118654752f));
                v2 = 0.5f * v2 * (1.0f + erff(v2 * 0.70710678118654752f));
                v3 = 0.5f * v3 * (1.0f + erff(v3 * 0.70710678118654752f));
            } else if (EPI == 3) {
                float4 cc = *(const float4*)(crow + cq * 4);
                v0 += cc.x; v1 += cc.y; v2 += cc.z; v3 += cc.w;
            }
            o.x = v0; o.y = v1; o.z = v2; o.w = v3;
            *(float4*)(crow + cq * 4) = o;
        }
    }
}

// ---------------------------------------------------------------------------
// Causal flash attention (fp32, online softmax, per-tile rescale).
// grid: (T/128, B*H), block 128 threads; each thread owns one query row.
// q/k/v layout: token-major (B*T, D); head h occupies cols [h*64, h*64+64).
// ---------------------------------------------------------------------------
#define KTILE 32

__global__ __launch_bounds__(128) void attn_kernel(
    const float* __restrict__ Q, const float* __restrict__ K,
    const float* __restrict__ V, float* __restrict__ O)
{
    const int tid = threadIdx.x;
    const int bh  = blockIdx.y;
    const int b   = bh / HH;
    const int h   = bh % HH;
    const int qi  = blockIdx.x * 128 + tid;       // global query index in [0,T)
    const int hoff = h * DHH;
    const long long tokbase = (long long)b * TT;

    __shared__ float Ks[KTILE][DHH];
    __shared__ float Vs[KTILE][DHH];

    // load this thread's query row into registers
    float qreg[DHH];
    {
        const float* qp = Q + (tokbase + qi) * DD + hoff;
        #pragma unroll
        for (int d4 = 0; d4 < DHH / 4; d4++) {
            float4 t = *(const float4*)(qp + d4 * 4);
            qreg[d4 * 4 + 0] = t.x; qreg[d4 * 4 + 1] = t.y;
            qreg[d4 * 4 + 2] = t.z; qreg[d4 * 4 + 3] = t.w;
        }
    }

    float m = -INFINITY, l = 0.f;
    float accv[DHH];
    #pragma unroll
    for (int d = 0; d < DHH; d++) accv[d] = 0.f;

    const int kmax = blockIdx.x * 128 + 127;      // last query this block serves
    const float scale = 0.125f;                   // 1/sqrt(64)

    for (int kt = 0; kt * KTILE <= kmax; kt++) {
        // cooperative load of K/V tile: 32x64 floats = 512 float4, 128 threads
        #pragma unroll
        for (int i = 0; i < 4; i++) {
            const int lin = tid + i * 128;
            const int row = lin >> 4;             // 0..31
            const int dq  = (lin & 15) << 2;      // 0..60 step 4
            const long long src = (tokbase + kt * KTILE + row) * DD + hoff + dq;
            *(float4*)&Ks[row][dq] = *(const float4*)(K + src);
            *(float4*)&Vs[row][dq] = *(const float4*)(V + src);
        }
        __syncthreads();

        float s[KTILE];
        float tmax = -INFINITY;
        #pragma unroll
        for (int j = 0; j < KTILE; j++) {
            const int kg = kt * KTILE + j;
            float dot = 0.f;
            #pragma unroll
            for (int d4 = 0; d4 < DHH / 4; d4++) {
                float4 kk = *(const float4*)&Ks[j][d4 * 4];
                dot += qreg[d4 * 4 + 0] * kk.x;
                dot += qreg[d4 * 4 + 1] * kk.y;
                dot += qreg[d4 * 4 + 2] * kk.z;
                dot += qreg[d4 * 4 + 3] * kk.w;
            }
            s[j] = (kg <= qi) ? dot * scale : -INFINITY;
            tmax = fmaxf(tmax, s[j]);
        }

        if (tmax > -1e30f) {                      // tile has at least one live key
            const float newm  = fmaxf(m, tmax);
            const float alpha = __expf(m - newm); // exp(-inf)=0 on first tile
            l *= alpha;
            #pragma unroll
            for (int d = 0; d < DHH; d++) accv[d] *= alpha;
            m = newm;
            #pragma unroll
            for (int j = 0; j < KTILE; j++) {
                const float p = __expf(s[j] - m); // exp(-inf)=0 for masked keys
                l += p;
                #pragma unroll
                for (int d4 = 0; d4 < DHH / 4; d4++) {
                    float4 vv = *(const float4*)&Vs[j][d4 * 4];
                    accv[d4 * 4 + 0] += p * vv.x;
                    accv[d4 * 4 + 1] += p * vv.y;
                    accv[d4 * 4 + 2] += p * vv.z;
                    accv[d4 * 4 + 3] += p * vv.w;
                }
            }
        }
        __syncthreads();
    }

    const float inv_l = 1.0f / l;
    float* op = O + (tokbase + qi) * DD + hoff;
    #pragma unroll
    for (int d4 = 0; d4 < DHH / 4; d4++) {
        float4 o;
        o.x = accv[d4 * 4 + 0] * inv_l;
        o.y = accv[d4 * 4 + 1] * inv_l;
        o.z = accv[d4 * 4 + 2] * inv_l;
        o.w = accv[d4 * 4 + 3] * inv_l;
        *(float4*)(op + d4 * 4) = o;
    }
}

// ---------------------------------------------------------------------------
// kernel_launch: LN1 -> QKV GEMMs -> attention -> Wo GEMM (+x residual, to out)
//                -> LN2 -> FF1 GEMM (+GELU) -> FF2 GEMM (accumulate into out)
// ---------------------------------------------------------------------------
extern "C" void kernel_launch(void* const* d_in, const int* in_sizes, int n_in,
                              void* d_out, int out_size)
{
    const float* x     = (const float*)d_in[0];
    // d_in[1] = causal mask (known structure; unused)
    const float* ln1_g = (const float*)d_in[2];
    const float* ln1_b = (const float*)d_in[3];
    const float* ln2_g = (const float*)d_in[4];
    const float* ln2_b = (const float*)d_in[5];
    const float* Wq    = (const float*)d_in[6];
    const float* Wk    = (const float*)d_in[7];
    const float* Wv    = (const float*)d_in[8];
    const float* Wo    = (const float*)d_in[9];
    const float* Wff1  = (const float*)d_in[10];
    const float* Wff2  = (const float*)d_in[11];
    float* out = (float*)d_out;

    float* s = nullptr;
    cudaGetSymbolAddress((void**)&s, g_scratch);
    float* h   = s;
    float* q   = s + 1 * SEG;
    float* k   = s + 2 * SEG;
    float* v   = s + 3 * SEG;
    float* att = s + 4 * SEG;
    float* ff  = s + 5 * SEG;

    const dim3 gD(DD / 128, ROWS / 128);    // (8, 32)
    const dim3 gF(FFD / 128, ROWS / 128);   // (32, 32)

    // 1. h = LN1(x)
    ln_kernel<<<ROWS, 256>>>(x, ln1_g, ln1_b, h);

    // 2. q/k/v projections
    gemm_tn<0><<<gD, 256>>>(h, Wq, q, nullptr, ROWS, DD, DD);
    gemm_tn<0><<<gD, 256>>>(h, Wk, k, nullptr, ROWS, DD, DD);
    gemm_tn<0><<<gD, 256>>>(h, Wv, v, nullptr, ROWS, DD, DD);

    // 3. causal attention
    attn_kernel<<<dim3(TT / 128, BB * HH), 128>>>(q, k, v, att);

    // 4. out = att @ Wo^T + x
    gemm_tn<1><<<gD, 256>>>(att, Wo, out, x, ROWS, DD, DD);

    // 5. h = LN2(out)
    ln_kernel<<<ROWS, 256>>>(out, ln2_g, ln2_b, h);

    // 6. ff = gelu(h @ Wff1^T)
    gemm_tn<2><<<gF, 256>>>(h, Wff1, ff, nullptr, ROWS, FFD, DD);

    // 7. out += ff @ Wff2^T
    gemm_tn<3><<<gD, 256>>>(ff, Wff2, out, nullptr, ROWS, DD, FFD);
}

// round 3
// speedup vs baseline: 1.9826x; 1.9826x over previous
#include <cuda_runtime.h>
#include <cuda_fp16.h>
#include <math.h>
#include <stdint.h>

// Problem constants
#define BB   2
#define TT   2048
#define DD   1024
#define HH   16
#define DHH  64
#define FFD  4096
#define ROWS (BB*TT)          // 4096
#define EPSF 1e-5f

// ---------------------------------------------------------------------------
// Scratch (no allocations allowed anywhere).
// ---------------------------------------------------------------------------
__device__ __align__(256) unsigned char g_scratch[172u * 1024u * 1024u];

// ---------------------------------------------------------------------------
// fp32 -> fp16 weight conversion (ternary weights are exact in fp16)
// ---------------------------------------------------------------------------
__global__ __launch_bounds__(256) void w2h_kernel(
    const float* __restrict__ w, __half* __restrict__ o)
{
    const int i = (blockIdx.x * 256 + threadIdx.x) * 4;
    float4 v = *(const float4*)(w + i);
    *(__half2*)(o + i)     = __floats2half2_rn(v.x, v.y);
    *(__half2*)(o + i + 2) = __floats2half2_rn(v.z, v.w);
}

// ---------------------------------------------------------------------------
// LayerNorm -> split hi/lo fp16 output. One block per row, 256 threads.
// ---------------------------------------------------------------------------
__global__ __launch_bounds__(256) void ln_split_kernel(
    const float* __restrict__ x, const float* __restrict__ g,
    const float* __restrict__ b, __half* __restrict__ ohi, __half* __restrict__ olo)
{
    const int row = blockIdx.x;
    const int tid = threadIdx.x;
    const float* xr = x + (size_t)row * DD;

    float4 v = *(const float4*)(xr + tid * 4);
    float s  = v.x + v.y + v.z + v.w;
    float ss = v.x * v.x + v.y * v.y + v.z * v.z + v.w * v.w;

    #pragma unroll
    for (int off = 16; off > 0; off >>= 1) {
        s  += __shfl_xor_sync(0xffffffff, s,  off);
        ss += __shfl_xor_sync(0xffffffff, ss, off);
    }
    __shared__ float sbuf[8], ssbuf[8];
    const int warp = tid >> 5, lane = tid & 31;
    if (lane == 0) { sbuf[warp] = s; ssbuf[warp] = ss; }
    __syncthreads();
    float S = 0.f, SS = 0.f;
    #pragma unroll
    for (int i = 0; i < 8; i++) { S += sbuf[i]; SS += ssbuf[i]; }

    const float mu  = S * (1.0f / DD);
    const float var = SS * (1.0f / DD) - mu * mu;
    const float rs  = rsqrtf(var + EPSF);

    float4 gg = *(const float4*)(g + tid * 4);
    float4 bb = *(const float4*)(b + tid * 4);
    float y0 = (v.x - mu) * rs * gg.x + bb.x;
    float y1 = (v.y - mu) * rs * gg.y + bb.y;
    float y2 = (v.z - mu) * rs * gg.z + bb.z;
    float y3 = (v.w - mu) * rs * gg.w + bb.w;

    __half h0 = __float2half_rn(y0), h1 = __float2half_rn(y1);
    __half h2 = __float2half_rn(y2), h3 = __float2half_rn(y3);
    const size_t base = (size_t)row * DD + tid * 4;
    *(__half2*)(ohi + base)     = __halves2half2(h0, h1);
    *(__half2*)(ohi + base + 2) = __halves2half2(h2, h3);
    *(__half2*)(olo + base)     = __halves2half2(
        __float2half_rn(y0 - __half2float(h0)), __float2half_rn(y1 - __half2float(h1)));
    *(__half2*)(olo + base + 2) = __halves2half2(
        __float2half_rn(y2 - __half2float(h2)), __float2half_rn(y3 - __half2float(h3)));
}

// ---------------------------------------------------------------------------
// fp16 split-A tensor-core GEMM: C[M,N] = (A_hi+A_lo)[M,K] @ W[N,K]^T
// 128x128 tile, BK=32 halves, 256 threads (8 warps 2x4), warp tile 64x32.
// mma.sync.m16n8k16 (2 per fragment: hi + lo), cp.async double-buffered,
// ldmatrix fragment loads, conflict-free smem (row stride 40 halves).
// EPI: 0 C=acc(f32), 1 C=acc+R(f32), 2 split(gelu(acc))->Ohi/Olo, 3 C+=acc
// ---------------------------------------------------------------------------
#define GM 128
#define GN 128
#define GK 32
#define GS 40            // half stride per row: 80B; 20 words -> all banks
#define STG (GM * GS)    // halves per stage per array

__device__ __forceinline__ void cp_async16(void* smem_dst, const void* gmem_src) {
    uint32_t s = (uint32_t)__cvta_generic_to_shared(smem_dst);
    asm volatile("cp.async.cg.shared.global [%0], [%1], 16;\n" :: "r"(s), "l"(gmem_src));
}
__device__ __forceinline__ void ldsm4(uint32_t* r, const __half* p) {
    uint32_t a = (uint32_t)__cvta_generic_to_shared(p);
    asm volatile("ldmatrix.sync.aligned.m8n8.x4.shared.b16 {%0,%1,%2,%3}, [%4];"
        : "=r"(r[0]), "=r"(r[1]), "=r"(r[2]), "=r"(r[3]) : "r"(a));
}
__device__ __forceinline__ void mma16816(float* c, const uint32_t* a, const uint32_t* b) {
    asm volatile(
        "mma.sync.aligned.m16n8k16.row.col.f32.f16.f16.f32 "
        "{%0,%1,%2,%3}, {%4,%5,%6,%7}, {%8,%9}, {%0,%1,%2,%3};"
        : "+f"(c[0]), "+f"(c[1]), "+f"(c[2]), "+f"(c[3])
        : "r"(a[0]), "r"(a[1]), "r"(a[2]), "r"(a[3]), "r"(b[0]), "r"(b[1]));
}

template<int EPI>
__global__ __launch_bounds__(256) void gemm_f16(
    const __half* __restrict__ Ah, const __half* __restrict__ Al,
    const __half* __restrict__ Wh, float* __restrict__ C,
    const float* __restrict__ R, __half* __restrict__ Ohi, __half* __restrict__ Olo,
    int M, int N, int K)
{
    extern __shared__ __half sm[];
    __half* sAh = sm;                // [2][STG]
    __half* sAl = sm + 2 * STG;
    __half* sW  = sm + 4 * STG;

    const int tid   = threadIdx.x;
    const int lane  = tid & 31;
    const int warp  = tid >> 5;
    const int wm    = (warp >> 2) * 64;
    const int wn    = (warp & 3) * 32;
    const int group = lane >> 2;
    const int t4    = lane & 3;

    const int bm = blockIdx.y * GM;
    const int bn = blockIdx.x * GN;

    // ldmatrix per-lane row/k offsets
    const int a_row = (lane & 7) + ((lane >> 3) & 1) * 8;
    const int a_k   = (lane >> 4) * 8;
    const int b_row = (lane & 7) + ((lane >> 4) & 1) * 8;
    const int b_k   = ((lane >> 3) & 1) * 8;

    float c[4][4][4];
    #pragma unroll
    for (int mi = 0; mi < 4; mi++)
        #pragma unroll
        for (int ni = 0; ni < 4; ni++)
            #pragma unroll
            for (int f = 0; f < 4; f++) c[mi][ni][f] = 0.f;

    const int KT = K / GK;

    // stage loader
    const int lrow = tid >> 2;            // 0..63 (x2 halves of the tile)
    const int lkc  = (tid & 3) * 8;       // 0,8,16,24 halves (16B chunks)

    #define STAGE_LOAD(st, k0)                                                      \
    {                                                                               \
        _Pragma("unroll")                                                           \
        for (int i = 0; i < 2; i++) {                                               \
            const int row = lrow + i * 64;                                          \
            const size_t ga = (size_t)(bm + row) * K + (k0) + lkc;                  \
            const size_t gw = (size_t)(bn + row) * K + (k0) + lkc;                  \
            cp_async16(&sAh[(st) * STG + row * GS + lkc], Ah + ga);                 \
            cp_async16(&sAl[(st) * STG + row * GS + lkc], Al + ga);                 \
            cp_async16(&sW [(st) * STG + row * GS + lkc], Wh + gw);                 \
        }                                                                           \
        asm volatile("cp.async.commit_group;\n");                                   \
    }

    STAGE_LOAD(0, 0)

    for (int kt = 0; kt < KT; kt++) {
        const int cur = kt & 1;
        if (kt + 1 < KT) {
            STAGE_LOAD(cur ^ 1, (kt + 1) * GK)
            asm volatile("cp.async.wait_group 1;\n");
        } else {
            asm volatile("cp.async.wait_group 0;\n");
        }
        __syncthreads();

        #pragma unroll
        for (int ks = 0; ks < GK; ks += 16) {
            uint32_t bf[4][2];
            #pragma unroll
            for (int ng = 0; ng < 2; ng++) {
                uint32_t r[4];
                ldsm4(r, &sW[cur * STG + (wn + ng * 16 + b_row) * GS + ks + b_k]);
                bf[2 * ng + 0][0] = r[0]; bf[2 * ng + 0][1] = r[1];
                bf[2 * ng + 1][0] = r[2]; bf[2 * ng + 1][1] = r[3];
            }
            #pragma unroll
            for (int mi = 0; mi < 4; mi++) {
                uint32_t ah[4], al[4];
                const int rb = (wm + mi * 16 + a_row) * GS + ks + a_k;
                ldsm4(ah, &sAh[cur * STG + rb]);
                ldsm4(al, &sAl[cur * STG + rb]);
                #pragma unroll
                for (int ni = 0; ni < 4; ni++) {
                    mma16816(c[mi][ni], ah, bf[ni]);
                    mma16816(c[mi][ni], al, bf[ni]);
                }
            }
        }
        __syncthreads();
    }

    // epilogue
    #pragma unroll
    for (int mi = 0; mi < 4; mi++) {
        #pragma unroll
        for (int hf = 0; hf < 2; hf++) {
            const int row = bm + wm + mi * 16 + group + hf * 8;
            #pragma unroll
            for (int ni = 0; ni < 4; ni++) {
                const int col = bn + wn + ni * 8 + t4 * 2;
                float v0 = c[mi][ni][hf * 2 + 0];
                float v1 = c[mi][ni][hf * 2 + 1];
                if (EPI == 0) {
                    float2 o; o.x = v0; o.y = v1;
                    *(float2*)(C + (size_t)row * N + col) = o;
                } else if (EPI == 1) {
                    float2 rr = *(const float2*)(R + (size_t)row * N + col);
                    float2 o; o.x = v0 + rr.x; o.y = v1 + rr.y;
                    *(float2*)(C + (size_t)row * N + col) = o;
                } else if (EPI == 2) {
                    float g0 = 0.5f * v0 * (1.0f + erff(v0 * 0.70710678118654752f));
                    float g1 = 0.5f * v1 * (1.0f + erff(v1 * 0.70710678118654752f));
                    __half h0 = __float2half_rn(g0), h1 = __float2half_rn(g1);
                    *(__half2*)(Ohi + (size_t)row * N + col) = __halves2half2(h0, h1);
                    *(__half2*)(Olo + (size_t)row * N + col) = __halves2half2(
                        __float2half_rn(g0 - __half2float(h0)),
                        __float2half_rn(g1 - __half2float(h1)));
                } else {
                    float2 cc = *(const float2*)(C + (size_t)row * N + col);
                    float2 o; o.x = v0 + cc.x; o.y = v1 + cc.y;
                    *(float2*)(C + (size_t)row * N + col) = o;
                }
            }
        }
    }
}

// ---------------------------------------------------------------------------
// Causal flash attention (fp32 SIMT) -> split hi/lo fp16 output.
// ---------------------------------------------------------------------------
#define KTILE 32

__global__ __launch_bounds__(128) void attn_kernel(
    const float* __restrict__ Q, const float* __restrict__ K,
    const float* __restrict__ V, __half* __restrict__ Ohi, __half* __restrict__ Olo)
{
    const int tid = threadIdx.x;
    const int bh  = blockIdx.y;
    const int b   = bh / HH;
    const int h   = bh % HH;
    const int qi  = blockIdx.x * 128 + tid;
    const int hoff = h * DHH;
    const long long tokbase = (long long)b * TT;

    __shared__ float Ks[KTILE][DHH];
    __shared__ float Vs[KTILE][DHH];

    float qreg[DHH];
    {
        const float* qp = Q + (tokbase + qi) * DD + hoff;
        #pragma unroll
        for (int d4 = 0; d4 < DHH / 4; d4++) {
            float4 t = *(const float4*)(qp + d4 * 4);
            qreg[d4 * 4 + 0] = t.x; qreg[d4 * 4 + 1] = t.y;
            qreg[d4 * 4 + 2] = t.z; qreg[d4 * 4 + 3] = t.w;
        }
    }

    float m = -INFINITY, l = 0.f;
    float accv[DHH];
    #pragma unroll
    for (int d = 0; d < DHH; d++) accv[d] = 0.f;

    const int kmax = blockIdx.x * 128 + 127;
    const float scale = 0.125f;

    for (int kt = 0; kt * KTILE <= kmax; kt++) {
        #pragma unroll
        for (int i = 0; i < 4; i++) {
            const int lin = tid + i * 128;
            const int row = lin >> 4;
            const int dq  = (lin & 15) << 2;
            const long long src = (tokbase + kt * KTILE + row) * DD + hoff + dq;
            *(float4*)&Ks[row][dq] = *(const float4*)(K + src);
            *(float4*)&Vs[row][dq] = *(const float4*)(V + src);
        }
        __syncthreads();

        float s[KTILE];
        float tmax = -INFINITY;
        #pragma unroll
        for (int j = 0; j < KTILE; j++) {
            const int kg = kt * KTILE + j;
            float dot = 0.f;
            #pragma unroll
            for (int d4 = 0; d4 < DHH / 4; d4++) {
                float4 kk = *(const float4*)&Ks[j][d4 * 4];
                dot += qreg[d4 * 4 + 0] * kk.x;
                dot += qreg[d4 * 4 + 1] * kk.y;
                dot += qreg[d4 * 4 + 2] * kk.z;
                dot += qreg[d4 * 4 + 3] * kk.w;
            }
            s[j] = (kg <= qi) ? dot * scale : -INFINITY;
            tmax = fmaxf(tmax, s[j]);
        }

        if (tmax > -1e30f) {
            const float newm  = fmaxf(m, tmax);
            const float alpha = __expf(m - newm);
            l *= alpha;
            #pragma unroll
            for (int d = 0; d < DHH; d++) accv[d] *= alpha;
            m = newm;
            #pragma unroll
            for (int j = 0; j < KTILE; j++) {
                const float p = __expf(s[j] - m);
                l += p;
                #pragma unroll
                for (int d4 = 0; d4 < DHH / 4; d4++) {
                    float4 vv = *(const float4*)&Vs[j][d4 * 4];
                    accv[d4 * 4 + 0] += p * vv.x;
                    accv[d4 * 4 + 1] += p * vv.y;
                    accv[d4 * 4 + 2] += p * vv.z;
                    accv[d4 * 4 + 3] += p * vv.w;
                }
            }
        }
        __syncthreads();
    }

    const float inv_l = 1.0f / l;
    const size_t obase = (size_t)(tokbase + qi) * DD + hoff;
    #pragma unroll
    for (int d2 = 0; d2 < DHH / 2; d2++) {
        float v0 = accv[d2 * 2 + 0] * inv_l;
        float v1 = accv[d2 * 2 + 1] * inv_l;
        __half h0 = __float2half_rn(v0), h1 = __float2half_rn(v1);
        *(__half2*)(Ohi + obase + d2 * 2) = __halves2half2(h0, h1);
        *(__half2*)(Olo + obase + d2 * 2) = __halves2half2(
            __float2half_rn(v0 - __half2float(h0)),
            __float2half_rn(v1 - __half2float(h1)));
    }
}

// ---------------------------------------------------------------------------
// kernel_launch
// ---------------------------------------------------------------------------
extern "C" void kernel_launch(void* const* d_in, const int* in_sizes, int n_in,
                              void* d_out, int out_size)
{
    const float* x     = (const float*)d_in[0];
    const float* ln1_g = (const float*)d_in[2];
    const float* ln1_b = (const float*)d_in[3];
    const float* ln2_g = (const float*)d_in[4];
    const float* ln2_b = (const float*)d_in[5];
    const float* Wq    = (const float*)d_in[6];
    const float* Wk    = (const float*)d_in[7];
    const float* Wv    = (const float*)d_in[8];
    const float* Wo    = (const float*)d_in[9];
    const float* Wff1  = (const float*)d_in[10];
    const float* Wff2  = (const float*)d_in[11];
    float* out = (float*)d_out;

    unsigned char* base = nullptr;
    cudaGetSymbolAddress((void**)&base, g_scratch);
    size_t off = 0;
    auto carve = [&](size_t bytes) { void* p = base + off; off += bytes; return p; };

    float*  q      = (float*) carve((size_t)ROWS * DD * 4);
    float*  k      = (float*) carve((size_t)ROWS * DD * 4);
    float*  v      = (float*) carve((size_t)ROWS * DD * 4);
    __half* h_hi   = (__half*)carve((size_t)ROWS * DD * 2);
    __half* h_lo   = (__half*)carve((size_t)ROWS * DD * 2);
    __half* att_hi = (__half*)carve((size_t)ROWS * DD * 2);
    __half* att_lo = (__half*)carve((size_t)ROWS * DD * 2);
    __half* ff_hi  = (__half*)carve((size_t)ROWS * FFD * 2);
    __half* ff_lo  = (__half*)carve((size_t)ROWS * FFD * 2);
    __half* Wq_h   = (__half*)carve((size_t)DD * DD * 2);
    __half* Wk_h   = (__half*)carve((size_t)DD * DD * 2);
    __half* Wv_h   = (__half*)carve((size_t)DD * DD * 2);
    __half* Wo_h   = (__half*)carve((size_t)DD * DD * 2);
    __half* Wf1_h  = (__half*)carve((size_t)FFD * DD * 2);
    __half* Wf2_h  = (__half*)carve((size_t)DD * FFD * 2);

    const size_t shmem = 6u * STG * sizeof(__half);   // 61440 bytes
    cudaFuncSetAttribute(gemm_f16<0>, cudaFuncAttributeMaxDynamicSharedMemorySize, (int)shmem);
    cudaFuncSetAttribute(gemm_f16<1>, cudaFuncAttributeMaxDynamicSharedMemorySize, (int)shmem);
    cudaFuncSetAttribute(gemm_f16<2>, cudaFuncAttributeMaxDynamicSharedMemorySize, (int)shmem);
    cudaFuncSetAttribute(gemm_f16<3>, cudaFuncAttributeMaxDynamicSharedMemorySize, (int)shmem);

    // weight conversion (ternary -> exact fp16)
    w2h_kernel<<<DD * DD / 1024, 256>>>(Wq, Wq_h);
    w2h_kernel<<<DD * DD / 1024, 256>>>(Wk, Wk_h);
    w2h_kernel<<<DD * DD / 1024, 256>>>(Wv, Wv_h);
    w2h_kernel<<<DD * DD / 1024, 256>>>(Wo, Wo_h);
    w2h_kernel<<<FFD * DD / 1024, 256>>>(Wff1, Wf1_h);
    w2h_kernel<<<FFD * DD / 1024, 256>>>(Wff2, Wf2_h);

    const dim3 gD(DD / GN, ROWS / GM);    // (8, 32)
    const dim3 gF(FFD / GN, ROWS / GM);   // (32, 32)

    ln_split_kernel<<<ROWS, 256>>>(x, ln1_g, ln1_b, h_hi, h_lo);

    gemm_f16<0><<<gD, 256, shmem>>>(h_hi, h_lo, Wq_h, q,  nullptr, nullptr, nullptr, ROWS, DD, DD);
    gemm_f16<0><<<gD, 256, shmem>>>(h_hi, h_lo, Wk_h, k,  nullptr, nullptr, nullptr, ROWS, DD, DD);
    gemm_f16<0><<<gD, 256, shmem>>>(h_hi, h_lo, Wv_h, v,  nullptr, nullptr, nullptr, ROWS, DD, DD);

    attn_kernel<<<dim3(TT / 128, BB * HH), 128>>>(q, k, v, att_hi, att_lo);

    gemm_f16<1><<<gD, 256, shmem>>>(att_hi, att_lo, Wo_h, out, x, nullptr, nullptr, ROWS, DD, DD);

    ln_split_kernel<<<ROWS, 256>>>(out, ln2_g, ln2_b, h_hi, h_lo);

    gemm_f16<2><<<gF, 256, shmem>>>(h_hi, h_lo, Wf1_h, nullptr, nullptr, ff_hi, ff_lo, ROWS, FFD, DD);

    gemm_f16<3><<<gD, 256, shmem>>>(ff_hi, ff_lo, Wf2_h, out, nullptr, nullptr, nullptr, ROWS, DD, FFD);
}

// round 4
// speedup vs baseline: 3.9237x; 1.9790x over previous
#include <cuda_runtime.h>
#include <cuda_fp16.h>
#include <math.h>
#include <stdint.h>

// Problem constants
#define BB   2
#define TT   2048
#define DD   1024
#define HH   16
#define DHH  64
#define FFD  4096
#define ROWS (BB*TT)          // 4096
#define EPSF 1e-5f

__device__ __align__(256) unsigned char g_scratch[168u * 1024u * 1024u];

// ---------------------------------------------------------------------------
// fp32 -> fp16 weight conversion (ternary weights exact in fp16)
// ---------------------------------------------------------------------------
__global__ __launch_bounds__(256) void w2h_kernel(
    const float* __restrict__ w, __half* __restrict__ o)
{
    const int i = (blockIdx.x * 256 + threadIdx.x) * 4;
    float4 v = *(const float4*)(w + i);
    *(__half2*)(o + i)     = __floats2half2_rn(v.x, v.y);
    *(__half2*)(o + i + 2) = __floats2half2_rn(v.z, v.w);
}

// ---------------------------------------------------------------------------
// LayerNorm -> split hi/lo fp16.
// ---------------------------------------------------------------------------
__global__ __launch_bounds__(256) void ln_split_kernel(
    const float* __restrict__ x, const float* __restrict__ g,
    const float* __restrict__ b, __half* __restrict__ ohi, __half* __restrict__ olo)
{
    const int row = blockIdx.x;
    const int tid = threadIdx.x;
    const float* xr = x + (size_t)row * DD;

    float4 v = *(const float4*)(xr + tid * 4);
    float s  = v.x + v.y + v.z + v.w;
    float ss = v.x * v.x + v.y * v.y + v.z * v.z + v.w * v.w;

    #pragma unroll
    for (int off = 16; off > 0; off >>= 1) {
        s  += __shfl_xor_sync(0xffffffff, s,  off);
        ss += __shfl_xor_sync(0xffffffff, ss, off);
    }
    __shared__ float sbuf[8], ssbuf[8];
    const int warp = tid >> 5, lane = tid & 31;
    if (lane == 0) { sbuf[warp] = s; ssbuf[warp] = ss; }
    __syncthreads();
    float S = 0.f, SS = 0.f;
    #pragma unroll
    for (int i = 0; i < 8; i++) { S += sbuf[i]; SS += ssbuf[i]; }

    const float mu  = S * (1.0f / DD);
    const float var = SS * (1.0f / DD) - mu * mu;
    const float rs  = rsqrtf(var + EPSF);

    float4 gg = *(const float4*)(g + tid * 4);
    float4 bb = *(const float4*)(b + tid * 4);
    float y0 = (v.x - mu) * rs * gg.x + bb.x;
    float y1 = (v.y - mu) * rs * gg.y + bb.y;
    float y2 = (v.z - mu) * rs * gg.z + bb.z;
    float y3 = (v.w - mu) * rs * gg.w + bb.w;

    __half h0 = __float2half_rn(y0), h1 = __float2half_rn(y1);
    __half h2 = __float2half_rn(y2), h3 = __float2half_rn(y3);
    const size_t base = (size_t)row * DD + tid * 4;
    *(__half2*)(ohi + base)     = __halves2half2(h0, h1);
    *(__half2*)(ohi + base + 2) = __halves2half2(h2, h3);
    *(__half2*)(olo + base)     = __halves2half2(
        __float2half_rn(y0 - __half2float(h0)), __float2half_rn(y1 - __half2float(h1)));
    *(__half2*)(olo + base + 2) = __halves2half2(
        __float2half_rn(y2 - __half2float(h2)), __float2half_rn(y3 - __half2float(h3)));
}

// ---------------------------------------------------------------------------
// MMA helpers
// ---------------------------------------------------------------------------
__device__ __forceinline__ void cp_async16(void* smem_dst, const void* gmem_src) {
    uint32_t s = (uint32_t)__cvta_generic_to_shared(smem_dst);
    asm volatile("cp.async.cg.shared.global [%0], [%1], 16;\n" :: "r"(s), "l"(gmem_src));
}
__device__ __forceinline__ void ldsm4(uint32_t* r, const __half* p) {
    uint32_t a = (uint32_t)__cvta_generic_to_shared(p);
    asm volatile("ldmatrix.sync.aligned.m8n8.x4.shared.b16 {%0,%1,%2,%3}, [%4];"
        : "=r"(r[0]), "=r"(r[1]), "=r"(r[2]), "=r"(r[3]) : "r"(a));
}
__device__ __forceinline__ void ldsm4t(uint32_t* r, const __half* p) {
    uint32_t a = (uint32_t)__cvta_generic_to_shared(p);
    asm volatile("ldmatrix.sync.aligned.m8n8.x4.trans.shared.b16 {%0,%1,%2,%3}, [%4];"
        : "=r"(r[0]), "=r"(r[1]), "=r"(r[2]), "=r"(r[3]) : "r"(a));
}
__device__ __forceinline__ void mma16816(float* c, const uint32_t* a, uint32_t b0, uint32_t b1) {
    asm volatile(
        "mma.sync.aligned.m16n8k16.row.col.f32.f16.f16.f32 "
        "{%0,%1,%2,%3}, {%4,%5,%6,%7}, {%8,%9}, {%0,%1,%2,%3};"
        : "+f"(c[0]), "+f"(c[1]), "+f"(c[2]), "+f"(c[3])
        : "r"(a[0]), "r"(a[1]), "r"(a[2]), "r"(a[3]), "r"(b0), "r"(b1));
}
__device__ __forceinline__ uint32_t h2ex2(uint32_t a) {
    uint32_t d;
    asm("ex2.approx.f16x2 %0, %1;" : "=r"(d) : "r"(a));
    return d;
}

// ---------------------------------------------------------------------------
// fp16 split-A tensor-core GEMM (as round 3), EPI:
//  1 C=acc+R (f32), 2 split(gelu(acc)) -> Ohi/Olo, 3 C+=acc, 4 split(acc)
// ---------------------------------------------------------------------------
#define GM 128
#define GN 128
#define GK 32
#define GS 40
#define STG (GM * GS)

template<int EPI>
__global__ __launch_bounds__(256) void gemm_f16(
    const __half* __restrict__ Ah, const __half* __restrict__ Al,
    const __half* __restrict__ Wh, float* __restrict__ C,
    const float* __restrict__ R, __half* __restrict__ Ohi, __half* __restrict__ Olo,
    int M, int N, int K)
{
    extern __shared__ __half sm[];
    __half* sAh = sm;
    __half* sAl = sm + 2 * STG;
    __half* sW  = sm + 4 * STG;

    const int tid   = threadIdx.x;
    const int lane  = tid & 31;
    const int warp  = tid >> 5;
    const int wm    = (warp >> 2) * 64;
    const int wn    = (warp & 3) * 32;
    const int group = lane >> 2;
    const int t4    = lane & 3;

    const int bm = blockIdx.y * GM;
    const int bn = blockIdx.x * GN;

    const int a_row = (lane & 7) + ((lane >> 3) & 1) * 8;
    const int a_k   = (lane >> 4) * 8;
    const int b_row = (lane & 7) + ((lane >> 4) & 1) * 8;
    const int b_k   = ((lane >> 3) & 1) * 8;

    float c[4][4][4];
    #pragma unroll
    for (int mi = 0; mi < 4; mi++)
        #pragma unroll
        for (int ni = 0; ni < 4; ni++)
            #pragma unroll
            for (int f = 0; f < 4; f++) c[mi][ni][f] = 0.f;

    const int KT = K / GK;
    const int lrow = tid >> 2;
    const int lkc  = (tid & 3) * 8;

    #define STAGE_LOAD(st, k0)                                                      \
    {                                                                               \
        _Pragma("unroll")                                                           \
        for (int i = 0; i < 2; i++) {                                               \
            const int row = lrow + i * 64;                                          \
            const size_t ga = (size_t)(bm + row) * K + (k0) + lkc;                  \
            const size_t gw = (size_t)(bn + row) * K + (k0) + lkc;                  \
            cp_async16(&sAh[(st) * STG + row * GS + lkc], Ah + ga);                 \
            cp_async16(&sAl[(st) * STG + row * GS + lkc], Al + ga);                 \
            cp_async16(&sW [(st) * STG + row * GS + lkc], Wh + gw);                 \
        }                                                                           \
        asm volatile("cp.async.commit_group;\n");                                   \
    }

    STAGE_LOAD(0, 0)

    for (int kt = 0; kt < KT; kt++) {
        const int cur = kt & 1;
        if (kt + 1 < KT) {
            STAGE_LOAD(cur ^ 1, (kt + 1) * GK)
            asm volatile("cp.async.wait_group 1;\n");
        } else {
            asm volatile("cp.async.wait_group 0;\n");
        }
        __syncthreads();

        #pragma unroll
        for (int ks = 0; ks < GK; ks += 16) {
            uint32_t bf[4][2];
            #pragma unroll
            for (int ng = 0; ng < 2; ng++) {
                uint32_t r[4];
                ldsm4(r, &sW[cur * STG + (wn + ng * 16 + b_row) * GS + ks + b_k]);
                bf[2 * ng + 0][0] = r[0]; bf[2 * ng + 0][1] = r[1];
                bf[2 * ng + 1][0] = r[2]; bf[2 * ng + 1][1] = r[3];
            }
            #pragma unroll
            for (int mi = 0; mi < 4; mi++) {
                uint32_t ah[4], al[4];
                const int rb = (wm + mi * 16 + a_row) * GS + ks + a_k;
                ldsm4(ah, &sAh[cur * STG + rb]);
                ldsm4(al, &sAl[cur * STG + rb]);
                #pragma unroll
                for (int ni = 0; ni < 4; ni++) {
                    mma16816(c[mi][ni], ah, bf[ni][0], bf[ni][1]);
                    mma16816(c[mi][ni], al, bf[ni][0], bf[ni][1]);
                }
            }
        }
        __syncthreads();
    }

    #pragma unroll
    for (int mi = 0; mi < 4; mi++) {
        #pragma unroll
        for (int hf = 0; hf < 2; hf++) {
            const int row = bm + wm + mi * 16 + group + hf * 8;
            #pragma unroll
            for (int ni = 0; ni < 4; ni++) {
                const int col = bn + wn + ni * 8 + t4 * 2;
                float v0 = c[mi][ni][hf * 2 + 0];
                float v1 = c[mi][ni][hf * 2 + 1];
                if (EPI == 1) {
                    float2 rr = *(const float2*)(R + (size_t)row * N + col);
                    float2 o; o.x = v0 + rr.x; o.y = v1 + rr.y;
                    *(float2*)(C + (size_t)row * N + col) = o;
                } else if (EPI == 2 || EPI == 4) {
                    if (EPI == 2) {
                        v0 = 0.5f * v0 * (1.0f + erff(v0 * 0.70710678118654752f));
                        v1 = 0.5f * v1 * (1.0f + erff(v1 * 0.70710678118654752f));
                    }
                    __half h0 = __float2half_rn(v0), h1 = __float2half_rn(v1);
                    *(__half2*)(Ohi + (size_t)row * N + col) = __halves2half2(h0, h1);
                    *(__half2*)(Olo + (size_t)row * N + col) = __halves2half2(
                        __float2half_rn(v0 - __half2float(h0)),
                        __float2half_rn(v1 - __half2float(h1)));
                } else {
                    float2 cc = *(const float2*)(C + (size_t)row * N + col);
                    float2 o; o.x = v0 + cc.x; o.y = v1 + cc.y;
                    *(float2*)(C + (size_t)row * N + col) = o;
                }
            }
        }
    }
}

// ---------------------------------------------------------------------------
// Tensor-core causal flash attention.
// Block: 256 thr (8 warps x 16 q-rows = 128 queries). K-tiles of 64 keys,
// double-buffered. S = QhKh+QlKh+QhKl; softmax base-2 via ex2.approx.f16x2;
// O += P@(Vh+Vl). fp32 accum. Output hi/lo fp16.
// ---------------------------------------------------------------------------
#define ATS 72                     // halves per row (64 + 8 pad; 144B = 9x16B)
#define QBUF (128 * ATS)           // one Q buffer (halves)
#define KVT  (64 * ATS)            // one K/V tile (halves)
#define KVSTG (4 * KVT)            // one stage: Kh,Kl,Vh,Vl
#define ASMEM ((2 * QBUF + 2 * KVSTG) * sizeof(__half))   // 110592 B

__global__ __launch_bounds__(256) void attn_tc(
    const __half* __restrict__ Qh, const __half* __restrict__ Ql,
    const __half* __restrict__ Kh, const __half* __restrict__ Kl,
    const __half* __restrict__ Vh, const __half* __restrict__ Vl,
    __half* __restrict__ Ohi, __half* __restrict__ Olo)
{
    extern __shared__ __half sm[];
    __half* sQh = sm;
    __half* sQl = sm + QBUF;
    __half* sKV = sm + 2 * QBUF;   // [2 stages][4 tiles][KVT]

    const int tid  = threadIdx.x;
    const int lane = tid & 31;
    const int warp = tid >> 5;
    const int wrow = warp * 16;
    const int group = lane >> 2;
    const int t4    = lane & 3;

    const int qtile = blockIdx.x;
    const int bh = blockIdx.y;
    const int b = bh >> 4, h = bh & 15;
    const int qbase = qtile * 128;
    const int hoff  = h * DHH;
    const size_t tokb = (size_t)b * TT;

    const int a_row = (lane & 7) + ((lane >> 3) & 1) * 8;
    const int a_k   = (lane >> 4) * 8;
    const int b_row = (lane & 7) + ((lane >> 4) & 1) * 8;   // K frags
    const int b_k   = ((lane >> 3) & 1) * 8;
    const int v_row = (lane & 7) + ((lane >> 3) & 1) * 8;   // V trans frags
    const int v_col = (lane >> 4) * 8;

    // ---- load Q (hi+lo) ----
    #pragma unroll
    for (int i = 0; i < 8; i++) {
        const int buf = i >> 2;                 // 0=hi 1=lo
        const int within = (i & 3) * 256 + tid; // 0..1023
        const int row = within >> 3;
        const int c8  = (within & 7) * 8;
        const __half* src = (buf == 0 ? Qh : Ql) + (tokb + qbase + row) * DD + hoff + c8;
        cp_async16((buf == 0 ? sQh : sQl) + row * ATS + c8, src);
    }
    asm volatile("cp.async.commit_group;\n");

    // ---- KV stage loader ----
    #define KV_LOAD(st, key0)                                                        \
    {                                                                                \
        _Pragma("unroll")                                                            \
        for (int i = 0; i < 8; i++) {                                                \
            const int tile = i >> 1;                                                 \
            const int row  = (i & 1) * 32 + (tid >> 3);                              \
            const int c8   = (tid & 7) * 8;                                          \
            const __half* src = (tile == 0 ? Kh : tile == 1 ? Kl :                   \
                                 tile == 2 ? Vh : Vl)                                \
                                + (tokb + (key0) + row) * DD + hoff + c8;            \
            cp_async16(&sKV[(st) * KVSTG + tile * KVT + row * ATS + c8], src);       \
        }                                                                            \
        asm volatile("cp.async.commit_group;\n");                                    \
    }

    KV_LOAD(0, 0)
    asm volatile("cp.async.wait_group 1;\n");   // Q ready
    __syncthreads();

    // ---- Q fragments to registers ----
    uint32_t qfh[4][4], qfl[4][4];
    #pragma unroll
    for (int kc = 0; kc < 4; kc++) {
        const int off = (wrow + a_row) * ATS + kc * 16 + a_k;
        ldsm4(qfh[kc], &sQh[off]);
        ldsm4(qfl[kc], &sQl[off]);
    }

    float o[8][4];
    #pragma unroll
    for (int ni = 0; ni < 8; ni++)
        #pragma unroll
        for (int f = 0; f < 4; f++) o[ni][f] = 0.f;
    float m0 = -INFINITY, m1 = -INFINITY, l0 = 0.f, l1 = 0.f;

    const float SC2 = 0.125f * 1.4426950408889634f;   // scale * log2(e)
    const int nkt = 2 * qtile + 2;

    for (int kt = 0; kt < nkt; kt++) {
        const int st = kt & 1;
        if (kt + 1 < nkt) {
            KV_LOAD(st ^ 1, (kt + 1) * 64)
            asm volatile("cp.async.wait_group 1;\n");
        } else {
            asm volatile("cp.async.wait_group 0;\n");
        }
        __syncthreads();

        const __half* pKh = &sKV[st * KVSTG + 0 * KVT];
        const __half* pKl = &sKV[st * KVSTG + 1 * KVT];
        const __half* pVh = &sKV[st * KVSTG + 2 * KVT];
        const __half* pVl = &sKV[st * KVSTG + 3 * KVT];

        // ---- S = Q K^T (split) ----
        float s[8][4];
        #pragma unroll
        for (int ni = 0; ni < 8; ni++)
            #pragma unroll
            for (int f = 0; f < 4; f++) s[ni][f] = 0.f;

        #pragma unroll
        for (int kc = 0; kc < 4; kc++) {
            #pragma unroll
            for (int ntp = 0; ntp < 4; ntp++) {
                uint32_t rh[4], rl[4];
                const int off = (ntp * 16 + b_row) * ATS + kc * 16 + b_k;
                ldsm4(rh, pKh + off);
                ldsm4(rl, pKl + off);
                mma16816(s[2*ntp+0], qfh[kc], rh[0], rh[1]);
                mma16816(s[2*ntp+1], qfh[kc], rh[2], rh[3]);
                mma16816(s[2*ntp+0], qfl[kc], rh[0], rh[1]);
                mma16816(s[2*ntp+1], qfl[kc], rh[2], rh[3]);
                mma16816(s[2*ntp+0], qfh[kc], rl[0], rl[1]);
                mma16816(s[2*ntp+1], qfh[kc], rl[2], rl[3]);
            }
        }

        // scale + causal mask
        const int r0 = qbase + wrow + group;
        const int r1 = r0 + 8;
        const bool needmask = (kt * 64 + 63) > (qbase + wrow);
        #pragma unroll
        for (int ni = 0; ni < 8; ni++) {
            #pragma unroll
            for (int f = 0; f < 4; f++) s[ni][f] *= SC2;
            if (needmask) {
                const int col = kt * 64 + ni * 8 + t4 * 2;
                if (col > r0)     s[ni][0] = -1e30f;
                if (col + 1 > r0) s[ni][1] = -1e30f;
                if (col > r1)     s[ni][2] = -1e30f;
                if (col + 1 > r1) s[ni][3] = -1e30f;
            }
        }

        // row max (quad reduce)
        float rm0 = -INFINITY, rm1 = -INFINITY;
        #pragma unroll
        for (int ni = 0; ni < 8; ni++) {
            rm0 = fmaxf(rm0, fmaxf(s[ni][0], s[ni][1]));
            rm1 = fmaxf(rm1, fmaxf(s[ni][2], s[ni][3]));
        }
        rm0 = fmaxf(rm0, __shfl_xor_sync(0xffffffff, rm0, 1));
        rm0 = fmaxf(rm0, __shfl_xor_sync(0xffffffff, rm0, 2));
        rm1 = fmaxf(rm1, __shfl_xor_sync(0xffffffff, rm1, 1));
        rm1 = fmaxf(rm1, __shfl_xor_sync(0xffffffff, rm1, 2));

        const float nm0 = fmaxf(m0, rm0), nm1 = fmaxf(m1, rm1);
        const float al0 = exp2f(m0 - nm0), al1 = exp2f(m1 - nm1);
        l0 *= al0; l1 *= al1;
        m0 = nm0; m1 = nm1;
        #pragma unroll
        for (int ni = 0; ni < 8; ni++) {
            o[ni][0] *= al0; o[ni][1] *= al0;
            o[ni][2] *= al1; o[ni][3] *= al1;
        }

        // p = exp2(s - m) in fp16x2
        uint32_t pf[8][2];
        float la0 = 0.f, la1 = 0.f;
        #pragma unroll
        for (int ni = 0; ni < 8; ni++) {
            __half2 t0 = __floats2half2_rn(fmaxf(s[ni][0] - m0, -60.f),
                                           fmaxf(s[ni][1] - m0, -60.f));
            __half2 t1 = __floats2half2_rn(fmaxf(s[ni][2] - m1, -60.f),
                                           fmaxf(s[ni][3] - m1, -60.f));
            uint32_t p0 = h2ex2(*(uint32_t*)&t0);
            uint32_t p1 = h2ex2(*(uint32_t*)&t1);
            pf[ni][0] = p0; pf[ni][1] = p1;
            float2 f0 = __half22float2(*(__half2*)&p0);
            float2 f1 = __half22float2(*(__half2*)&p1);
            la0 += f0.x + f0.y;
            la1 += f1.x + f1.y;
        }
        la0 += __shfl_xor_sync(0xffffffff, la0, 1);
        la0 += __shfl_xor_sync(0xffffffff, la0, 2);
        la1 += __shfl_xor_sync(0xffffffff, la1, 1);
        la1 += __shfl_xor_sync(0xffffffff, la1, 2);
        l0 += la0; l1 += la1;

        // O += P @ (Vh + Vl)
        #pragma unroll
        for (int kc = 0; kc < 4; kc++) {
            uint32_t a[4] = { pf[2*kc][0], pf[2*kc][1], pf[2*kc+1][0], pf[2*kc+1][1] };
            #pragma unroll
            for (int ntp = 0; ntp < 4; ntp++) {
                uint32_t rh[4], rl[4];
                const int off = (kc * 16 + v_row) * ATS + ntp * 16 + v_col;
                ldsm4t(rh, pVh + off);
                ldsm4t(rl, pVl + off);
                mma16816(o[2*ntp+0], a, rh[0], rh[1]);
                mma16816(o[2*ntp+1], a, rh[2], rh[3]);
                mma16816(o[2*ntp+0], a, rl[0], rl[1]);
                mma16816(o[2*ntp+1], a, rl[2], rl[3]);
            }
        }
        __syncthreads();
    }

    // epilogue: normalize + hi/lo split store
    const float il0 = 1.0f / l0, il1 = 1.0f / l1;
    const size_t gr0 = (tokb + qbase + wrow + group) * DD + hoff;
    const size_t gr1 = gr0 + 8 * DD;
    #pragma unroll
    for (int ni = 0; ni < 8; ni++) {
        const int col = ni * 8 + t4 * 2;
        float v0 = o[ni][0] * il0, v1 = o[ni][1] * il0;
        float v2 = o[ni][2] * il1, v3 = o[ni][3] * il1;
        __half h0 = __float2half_rn(v0), h1 = __float2half_rn(v1);
        __half h2c = __float2half_rn(v2), h3 = __float2half_rn(v3);
        *(__half2*)(Ohi + gr0 + col) = __halves2half2(h0, h1);
        *(__half2*)(Olo + gr0 + col) = __halves2half2(
            __float2half_rn(v0 - __half2float(h0)), __float2half_rn(v1 - __half2float(h1)));
        *(__half2*)(Ohi + gr1 + col) = __halves2half2(h2c, h3);
        *(__half2*)(Olo + gr1 + col) = __halves2half2(
            __float2half_rn(v2 - __half2float(h2c)), __float2half_rn(v3 - __half2float(h3)));
    }
}

// ---------------------------------------------------------------------------
// kernel_launch
// ---------------------------------------------------------------------------
extern "C" void kernel_launch(void* const* d_in, const int* in_sizes, int n_in,
                              void* d_out, int out_size)
{
    const float* x     = (const float*)d_in[0];
    const float* ln1_g = (const float*)d_in[2];
    const float* ln1_b = (const float*)d_in[3];
    const float* ln2_g = (const float*)d_in[4];
    const float* ln2_b = (const float*)d_in[5];
    const float* Wq    = (const float*)d_in[6];
    const float* Wk    = (const float*)d_in[7];
    const float* Wv    = (const float*)d_in[8];
    const float* Wo    = (const float*)d_in[9];
    const float* Wff1  = (const float*)d_in[10];
    const float* Wff2  = (const float*)d_in[11];
    float* out = (float*)d_out;

    unsigned char* base = nullptr;
    cudaGetSymbolAddress((void**)&base, g_scratch);
    size_t off = 0;
    auto carve = [&](size_t bytes) { void* p = base + off; off += bytes; return p; };

    __half* qhh    = (__half*)carve((size_t)ROWS * DD * 2);
    __half* qhl    = (__half*)carve((size_t)ROWS * DD * 2);
    __half* khh    = (__half*)carve((size_t)ROWS * DD * 2);
    __half* khl    = (__half*)carve((size_t)ROWS * DD * 2);
    __half* vhh    = (__half*)carve((size_t)ROWS * DD * 2);
    __half* vhl    = (__half*)carve((size_t)ROWS * DD * 2);
    __half* h_hi   = (__half*)carve((size_t)ROWS * DD * 2);
    __half* h_lo   = (__half*)carve((size_t)ROWS * DD * 2);
    __half* att_hi = (__half*)carve((size_t)ROWS * DD * 2);
    __half* att_lo = (__half*)carve((size_t)ROWS * DD * 2);
    __half* ff_hi  = (__half*)carve((size_t)ROWS * FFD * 2);
    __half* ff_lo  = (__half*)carve((size_t)ROWS * FFD * 2);
    __half* Wq_h   = (__half*)carve((size_t)DD * DD * 2);
    __half* Wk_h   = (__half*)carve((size_t)DD * DD * 2);
    __half* Wv_h   = (__half*)carve((size_t)DD * DD * 2);
    __half* Wo_h   = (__half*)carve((size_t)DD * DD * 2);
    __half* Wf1_h  = (__half*)carve((size_t)FFD * DD * 2);
    __half* Wf2_h  = (__half*)carve((size_t)DD * FFD * 2);

    const size_t shmem = 6u * STG * sizeof(__half);
    cudaFuncSetAttribute(gemm_f16<1>, cudaFuncAttributeMaxDynamicSharedMemorySize, (int)shmem);
    cudaFuncSetAttribute(gemm_f16<2>, cudaFuncAttributeMaxDynamicSharedMemorySize, (int)shmem);
    cudaFuncSetAttribute(gemm_f16<3>, cudaFuncAttributeMaxDynamicSharedMemorySize, (int)shmem);
    cudaFuncSetAttribute(gemm_f16<4>, cudaFuncAttributeMaxDynamicSharedMemorySize, (int)shmem);
    cudaFuncSetAttribute(attn_tc, cudaFuncAttributeMaxDynamicSharedMemorySize, (int)ASMEM);

    w2h_kernel<<<DD * DD / 1024, 256>>>(Wq, Wq_h);
    w2h_kernel<<<DD * DD / 1024, 256>>>(Wk, Wk_h);
    w2h_kernel<<<DD * DD / 1024, 256>>>(Wv, Wv_h);
    w2h_kernel<<<DD * DD / 1024, 256>>>(Wo, Wo_h);
    w2h_kernel<<<FFD * DD / 1024, 256>>>(Wff1, Wf1_h);
    w2h_kernel<<<FFD * DD / 1024, 256>>>(Wff2, Wf2_h);

    const dim3 gD(DD / GN, ROWS / GM);
    const dim3 gF(FFD / GN, ROWS / GM);

    ln_split_kernel<<<ROWS, 256>>>(x, ln1_g, ln1_b, h_hi, h_lo);

    gemm_f16<4><<<gD, 256, shmem>>>(h_hi, h_lo, Wq_h, nullptr, nullptr, qhh, qhl, ROWS, DD, DD);
    gemm_f16<4><<<gD, 256, shmem>>>(h_hi, h_lo, Wk_h, nullptr, nullptr, khh, khl, ROWS, DD, DD);
    gemm_f16<4><<<gD, 256, shmem>>>(h_hi, h_lo, Wv_h, nullptr, nullptr, vhh, vhl, ROWS, DD, DD);

    attn_tc<<<dim3(TT / 128, BB * HH), 256, ASMEM>>>(qhh, qhl, khh, khl, vhh, vhl, att_hi, att_lo);

    gemm_f16<1><<<gD, 256, shmem>>>(att_hi, att_lo, Wo_h, out, x, nullptr, nullptr, ROWS, DD, DD);

    ln_split_kernel<<<ROWS, 256>>>(out, ln2_g, ln2_b, h_hi, h_lo);

    gemm_f16<2><<<gF, 256, shmem>>>(h_hi, h_lo, Wf1_h, nullptr, nullptr, ff_hi, ff_lo, ROWS, FFD, DD);

    gemm_f16<3><<<gD, 256, shmem>>>(ff_hi, ff_lo, Wf2_h, out, nullptr, nullptr, nullptr, ROWS, DD, FFD);
}

// round 5
// speedup vs baseline: 4.1095x; 1.0474x over previous
#include <cuda_runtime.h>
#include <cuda_fp16.h>
#include <math.h>
#include <stdint.h>

// Problem constants
#define BB   2
#define TT   2048
#define DD   1024
#define HH   16
#define DHH  64
#define FFD  4096
#define ROWS (BB*TT)          // 4096
#define SEG  (ROWS * DD)      // 4194304 elements
#define EPSF 1e-5f

__device__ __align__(256) unsigned char g_scratch[190u * 1024u * 1024u];

// ---------------------------------------------------------------------------
// fused fp32 -> fp16 weight conversion
// ---------------------------------------------------------------------------
__global__ __launch_bounds__(256) void w2h_attn(
    const float* __restrict__ s0, const float* __restrict__ s1,
    const float* __restrict__ s2, const float* __restrict__ s3,
    __half* __restrict__ dst)
{
    const size_t idx = ((size_t)blockIdx.x * 256 + threadIdx.x) * 4;  // 4x 1M elems
    const int seg = (int)(idx >> 20);
    const float* s = (seg == 0) ? s0 : (seg == 1) ? s1 : (seg == 2) ? s2 : s3;
    float4 v = *(const float4*)(s + (idx & 0xFFFFF));
    *(__half2*)(dst + idx)     = __floats2half2_rn(v.x, v.y);
    *(__half2*)(dst + idx + 2) = __floats2half2_rn(v.z, v.w);
}
__global__ __launch_bounds__(256) void w2h_ff(
    const float* __restrict__ s0, const float* __restrict__ s1,
    __half* __restrict__ dst)
{
    const size_t idx = ((size_t)blockIdx.x * 256 + threadIdx.x) * 4;  // 2x 4M elems
    const int seg = (int)(idx >> 22);
    const float* s = (seg == 0) ? s0 : s1;
    float4 v = *(const float4*)(s + (idx & 0x3FFFFF));
    *(__half2*)(dst + idx)     = __floats2half2_rn(v.x, v.y);
    *(__half2*)(dst + idx + 2) = __floats2half2_rn(v.z, v.w);
}

// ---------------------------------------------------------------------------
// LayerNorm -> split hi/lo fp16.
// ---------------------------------------------------------------------------
__global__ __launch_bounds__(256) void ln_split_kernel(
    const float* __restrict__ x, const float* __restrict__ g,
    const float* __restrict__ b, __half* __restrict__ ohi, __half* __restrict__ olo)
{
    const int row = blockIdx.x;
    const int tid = threadIdx.x;
    const float* xr = x + (size_t)row * DD;

    float4 v = *(const float4*)(xr + tid * 4);
    float s  = v.x + v.y + v.z + v.w;
    float ss = v.x * v.x + v.y * v.y + v.z * v.z + v.w * v.w;

    #pragma unroll
    for (int off = 16; off > 0; off >>= 1) {
        s  += __shfl_xor_sync(0xffffffff, s,  off);
        ss += __shfl_xor_sync(0xffffffff, ss, off);
    }
    __shared__ float sbuf[8], ssbuf[8];
    const int warp = tid >> 5, lane = tid & 31;
    if (lane == 0) { sbuf[warp] = s; ssbuf[warp] = ss; }
    __syncthreads();
    float S = 0.f, SS = 0.f;
    #pragma unroll
    for (int i = 0; i < 8; i++) { S += sbuf[i]; SS += ssbuf[i]; }

    const float mu  = S * (1.0f / DD);
    const float var = SS * (1.0f / DD) - mu * mu;
    const float rs  = rsqrtf(var + EPSF);

    float4 gg = *(const float4*)(g + tid * 4);
    float4 bb = *(const float4*)(b + tid * 4);
    float y0 = (v.x - mu) * rs * gg.x + bb.x;
    float y1 = (v.y - mu) * rs * gg.y + bb.y;
    float y2 = (v.z - mu) * rs * gg.z + bb.z;
    float y3 = (v.w - mu) * rs * gg.w + bb.w;

    __half h0 = __float2half_rn(y0), h1 = __float2half_rn(y1);
    __half h2 = __float2half_rn(y2), h3 = __float2half_rn(y3);
    const size_t base = (size_t)row * DD + tid * 4;
    *(__half2*)(ohi + base)     = __halves2half2(h0, h1);
    *(__half2*)(ohi + base + 2) = __halves2half2(h2, h3);
    *(__half2*)(olo + base)     = __halves2half2(
        __float2half_rn(y0 - __half2float(h0)), __float2half_rn(y1 - __half2float(h1)));
    *(__half2*)(olo + base + 2) = __halves2half2(
        __float2half_rn(y2 - __half2float(h2)), __float2half_rn(y3 - __half2float(h3)));
}

// ---------------------------------------------------------------------------
// MMA helpers
// ---------------------------------------------------------------------------
__device__ __forceinline__ void cp_async16(void* smem_dst, const void* gmem_src) {
    uint32_t s = (uint32_t)__cvta_generic_to_shared(smem_dst);
    asm volatile("cp.async.cg.shared.global [%0], [%1], 16;\n" :: "r"(s), "l"(gmem_src));
}
__device__ __forceinline__ void ldsm4(uint32_t* r, const __half* p) {
    uint32_t a = (uint32_t)__cvta_generic_to_shared(p);
    asm volatile("ldmatrix.sync.aligned.m8n8.x4.shared.b16 {%0,%1,%2,%3}, [%4];"
        : "=r"(r[0]), "=r"(r[1]), "=r"(r[2]), "=r"(r[3]) : "r"(a));
}
__device__ __forceinline__ void ldsm4t(uint32_t* r, const __half* p) {
    uint32_t a = (uint32_t)__cvta_generic_to_shared(p);
    asm volatile("ldmatrix.sync.aligned.m8n8.x4.trans.shared.b16 {%0,%1,%2,%3}, [%4];"
        : "=r"(r[0]), "=r"(r[1]), "=r"(r[2]), "=r"(r[3]) : "r"(a));
}
__device__ __forceinline__ void mma16816(float* c, const uint32_t* a, uint32_t b0, uint32_t b1) {
    asm volatile(
        "mma.sync.aligned.m16n8k16.row.col.f32.f16.f16.f32 "
        "{%0,%1,%2,%3}, {%4,%5,%6,%7}, {%8,%9}, {%0,%1,%2,%3};"
        : "+f"(c[0]), "+f"(c[1]), "+f"(c[2]), "+f"(c[3])
        : "r"(a[0]), "r"(a[1]), "r"(a[2]), "r"(a[3]), "r"(b0), "r"(b1));
}
__device__ __forceinline__ uint32_t h2ex2(uint32_t a) {
    uint32_t d;
    asm("ex2.approx.f16x2 %0, %1;" : "=r"(d) : "r"(a));
    return d;
}

// ---------------------------------------------------------------------------
// fp16 split-A GEMM: C[M,N] = (A_hi+A_lo)[M,K] @ W[N,K]^T
// 128x128 tile, BK=32, 3-stage cp.async pipeline, 8 warps (2x4), 64x32/warp.
// EPI: 1 C=acc+R(f32), 2 split(gelu)->Ohi/Olo, 3 C+=acc,
//      5 segmented split store (QKV fused: col>>10 picks segment of SEG elems)
// ---------------------------------------------------------------------------
#define GM 128
#define GN 128
#define GK 32
#define GS 40
#define STG (GM * GS)          // halves per tile array
#define GSTAGE (3 * STG)       // Ah + Al + W per stage
#define GSMEM (3u * GSTAGE * sizeof(__half))   // 92160 B

template<int EPI>
__global__ __launch_bounds__(256) void gemm_f16(
    const __half* __restrict__ Ah, const __half* __restrict__ Al,
    const __half* __restrict__ Wh, float* __restrict__ C,
    const float* __restrict__ R, __half* __restrict__ Ohi, __half* __restrict__ Olo,
    int M, int N, int K)
{
    extern __shared__ __half sm[];

    const int tid   = threadIdx.x;
    const int lane  = tid & 31;
    const int warp  = tid >> 5;
    const int wm    = (warp >> 2) * 64;
    const int wn    = (warp & 3) * 32;
    const int group = lane >> 2;
    const int t4    = lane & 3;

    const int bm = blockIdx.y * GM;
    const int bn = blockIdx.x * GN;

    const int a_row = (lane & 7) + ((lane >> 3) & 1) * 8;
    const int a_k   = (lane >> 4) * 8;
    const int b_row = (lane & 7) + ((lane >> 4) & 1) * 8;
    const int b_k   = ((lane >> 3) & 1) * 8;

    float c[4][4][4];
    #pragma unroll
    for (int mi = 0; mi < 4; mi++)
        #pragma unroll
        for (int ni = 0; ni < 4; ni++)
            #pragma unroll
            for (int f = 0; f < 4; f++) c[mi][ni][f] = 0.f;

    const int KT = K / GK;
    const int lrow = tid >> 2;
    const int lkc  = (tid & 3) * 8;

    #define STAGE_LOAD(st, k0)                                                      \
    {                                                                               \
        __half* sAh = sm + (st) * GSTAGE;                                           \
        __half* sAl = sAh + STG;                                                    \
        __half* sW  = sAh + 2 * STG;                                                \
        _Pragma("unroll")                                                           \
        for (int i = 0; i < 2; i++) {                                               \
            const int row = lrow + i * 64;                                          \
            const size_t ga = (size_t)(bm + row) * K + (k0) + lkc;                  \
            const size_t gw = (size_t)(bn + row) * K + (k0) + lkc;                  \
            cp_async16(&sAh[row * GS + lkc], Ah + ga);                              \
            cp_async16(&sAl[row * GS + lkc], Al + ga);                              \
            cp_async16(&sW [row * GS + lkc], Wh + gw);                              \
        }                                                                           \
        asm volatile("cp.async.commit_group;\n");                                   \
    }

    STAGE_LOAD(0, 0)
    STAGE_LOAD(1, GK)

    for (int kt = 0; kt < KT; kt++) {
        if (kt + 2 < KT) {
            STAGE_LOAD((kt + 2) % 3, (kt + 2) * GK)
            asm volatile("cp.async.wait_group 2;\n");
        } else if (kt + 1 < KT) {
            asm volatile("cp.async.wait_group 1;\n");
        } else {
            asm volatile("cp.async.wait_group 0;\n");
        }
        __syncthreads();

        const int cs = kt % 3;
        const __half* sAh = sm + cs * GSTAGE;
        const __half* sAl = sAh + STG;
        const __half* sW  = sAh + 2 * STG;

        #pragma unroll
        for (int ks = 0; ks < GK; ks += 16) {
            uint32_t bf[4][2];
            #pragma unroll
            for (int ng = 0; ng < 2; ng++) {
                uint32_t r[4];
                ldsm4(r, &sW[(wn + ng * 16 + b_row) * GS + ks + b_k]);
                bf[2 * ng + 0][0] = r[0]; bf[2 * ng + 0][1] = r[1];
                bf[2 * ng + 1][0] = r[2]; bf[2 * ng + 1][1] = r[3];
            }
            #pragma unroll
            for (int mi = 0; mi < 4; mi++) {
                uint32_t ah[4], al[4];
                const int rb = (wm + mi * 16 + a_row) * GS + ks + a_k;
                ldsm4(ah, &sAh[rb]);
                ldsm4(al, &sAl[rb]);
                #pragma unroll
                for (int ni = 0; ni < 4; ni++) {
                    mma16816(c[mi][ni], ah, bf[ni][0], bf[ni][1]);
                    mma16816(c[mi][ni], al, bf[ni][0], bf[ni][1]);
                }
            }
        }
        __syncthreads();
    }

    #pragma unroll
    for (int mi = 0; mi < 4; mi++) {
        #pragma unroll
        for (int hf = 0; hf < 2; hf++) {
            const int row = bm + wm + mi * 16 + group + hf * 8;
            #pragma unroll
            for (int ni = 0; ni < 4; ni++) {
                const int col = bn + wn + ni * 8 + t4 * 2;
                float v0 = c[mi][ni][hf * 2 + 0];
                float v1 = c[mi][ni][hf * 2 + 1];
                if (EPI == 1) {
                    float2 rr = *(const float2*)(R + (size_t)row * N + col);
                    float2 o; o.x = v0 + rr.x; o.y = v1 + rr.y;
                    *(float2*)(C + (size_t)row * N + col) = o;
                } else if (EPI == 2) {
                    v0 = 0.5f * v0 * (1.0f + erff(v0 * 0.70710678118654752f));
                    v1 = 0.5f * v1 * (1.0f + erff(v1 * 0.70710678118654752f));
                    __half h0 = __float2half_rn(v0), h1 = __float2half_rn(v1);
                    *(__half2*)(Ohi + (size_t)row * N + col) = __halves2half2(h0, h1);
                    *(__half2*)(Olo + (size_t)row * N + col) = __halves2half2(
                        __float2half_rn(v0 - __half2float(h0)),
                        __float2half_rn(v1 - __half2float(h1)));
                } else if (EPI == 5) {
                    const int seg = col >> 10;
                    const int lc  = col & 1023;
                    const size_t di = ((size_t)seg * ROWS + row) * DD + lc;
                    __half h0 = __float2half_rn(v0), h1 = __float2half_rn(v1);
                    *(__half2*)(Ohi + di) = __halves2half2(h0, h1);
                    *(__half2*)(Olo + di) = __halves2half2(
                        __float2half_rn(v0 - __half2float(h0)),
                        __float2half_rn(v1 - __half2float(h1)));
                } else {  // EPI == 3
                    float2 cc = *(const float2*)(C + (size_t)row * N + col);
                    float2 o; o.x = v0 + cc.x; o.y = v1 + cc.y;
                    *(float2*)(C + (size_t)row * N + col) = o;
                }
            }
        }
    }
}

// ---------------------------------------------------------------------------
// Tensor-core causal flash attention. 256 thr, 8 warps x 16 q-rows.
// K-tiles of 64 keys double-buffered; Q parked in stage-1 region (overlay).
// ---------------------------------------------------------------------------
#define ATS 72
#define QBUF (128 * ATS)           // halves (= 18432 B); 2*QBUF == KVSTG
#define KVT  (64 * ATS)
#define KVSTG (4 * KVT)
#define ASMEM (2u * KVSTG * sizeof(__half))   // 73728 B

__global__ __launch_bounds__(256) void attn_tc(
    const __half* __restrict__ Qh, const __half* __restrict__ Ql,
    const __half* __restrict__ Kh, const __half* __restrict__ Kl,
    const __half* __restrict__ Vh, const __half* __restrict__ Vl,
    __half* __restrict__ Ohi, __half* __restrict__ Olo)
{
    extern __shared__ __half sm[];
    __half* sKV = sm;                         // [2][KVSTG]
    __half* sQh = sm + KVSTG;                 // overlay on stage 1
    __half* sQl = sQh + QBUF;

    const int tid  = threadIdx.x;
    const int lane = tid & 31;
    const int warp = tid >> 5;
    const int wrow = warp * 16;
    const int group = lane >> 2;
    const int t4    = lane & 3;

    const int qtile = gridDim.x - 1 - blockIdx.x;   // long blocks first
    const int bh = blockIdx.y;
    const int b = bh >> 4, h = bh & 15;
    const int qbase = qtile * 128;
    const int hoff  = h * DHH;
    const size_t tokb = (size_t)b * TT;

    const int a_row = (lane & 7) + ((lane >> 3) & 1) * 8;
    const int a_k   = (lane >> 4) * 8;
    const int b_row = (lane & 7) + ((lane >> 4) & 1) * 8;
    const int b_k   = ((lane >> 3) & 1) * 8;
    const int v_row = (lane & 7) + ((lane >> 3) & 1) * 8;
    const int v_col = (lane >> 4) * 8;

    // ---- stage Q (into overlay) ----
    #pragma unroll
    for (int i = 0; i < 8; i++) {
        const int buf = i >> 2;
        const int within = (i & 3) * 256 + tid;
        const int row = within >> 3;
        const int c8  = (within & 7) * 8;
        const __half* src = (buf == 0 ? Qh : Ql) + (tokb + qbase + row) * DD + hoff + c8;
        cp_async16((buf == 0 ? sQh : sQl) + row * ATS + c8, src);
    }
    asm volatile("cp.async.commit_group;\n");

    #define KV_LOAD(st, key0)                                                        \
    {                                                                                \
        _Pragma("unroll")                                                            \
        for (int i = 0; i < 8; i++) {                                                \
            const int tile = i >> 1;                                                 \
            const int row  = (i & 1) * 32 + (tid >> 3);                              \
            const int c8   = (tid & 7) * 8;                                          \
            const __half* src = (tile == 0 ? Kh : tile == 1 ? Kl :                   \
                                 tile == 2 ? Vh : Vl)                                \
                                + (tokb + (key0) + row) * DD + hoff + c8;            \
            cp_async16(&sKV[(st) * KVSTG + tile * KVT + row * ATS + c8], src);       \
        }                                                                            \
        asm volatile("cp.async.commit_group;\n");                                    \
    }

    KV_LOAD(0, 0)
    asm volatile("cp.async.wait_group 1;\n");   // Q complete
    __syncthreads();

    uint32_t qfh[4][4], qfl[4][4];
    #pragma unroll
    for (int kc = 0; kc < 4; kc++) {
        const int off = (wrow + a_row) * ATS + kc * 16 + a_k;
        ldsm4(qfh[kc], &sQh[off]);
        ldsm4(qfl[kc], &sQl[off]);
    }
    __syncthreads();   // all warps done reading Q before stage-1 reuse

    float o[8][4];
    #pragma unroll
    for (int ni = 0; ni < 8; ni++)
        #pragma unroll
        for (int f = 0; f < 4; f++) o[ni][f] = 0.f;
    float m0 = -INFINITY, m1 = -INFINITY, l0 = 0.f, l1 = 0.f;

    const float SC2 = 0.125f * 1.4426950408889634f;
    const int nkt = 2 * qtile + 2;

    for (int kt = 0; kt < nkt; kt++) {
        const int st = kt & 1;
        if (kt + 1 < nkt) {
            KV_LOAD(st ^ 1, (kt + 1) * 64)
            asm volatile("cp.async.wait_group 1;\n");
        } else {
            asm volatile("cp.async.wait_group 0;\n");
        }
        __syncthreads();

        const __half* pKh = &sKV[st * KVSTG + 0 * KVT];
        const __half* pKl = &sKV[st * KVSTG + 1 * KVT];
        const __half* pVh = &sKV[st * KVSTG + 2 * KVT];
        const __half* pVl = &sKV[st * KVSTG + 3 * KVT];

        float s[8][4];
        #pragma unroll
        for (int ni = 0; ni < 8; ni++)
            #pragma unroll
            for (int f = 0; f < 4; f++) s[ni][f] = 0.f;

        #pragma unroll
        for (int kc = 0; kc < 4; kc++) {
            #pragma unroll
            for (int ntp = 0; ntp < 4; ntp++) {
                uint32_t rh[4], rl[4];
                const int off = (ntp * 16 + b_row) * ATS + kc * 16 + b_k;
                ldsm4(rh, pKh + off);
                ldsm4(rl, pKl + off);
                mma16816(s[2*ntp+0], qfh[kc], rh[0], rh[1]);
                mma16816(s[2*ntp+1], qfh[kc], rh[2], rh[3]);
                mma16816(s[2*ntp+0], qfl[kc], rh[0], rh[1]);
                mma16816(s[2*ntp+1], qfl[kc], rh[2], rh[3]);
                mma16816(s[2*ntp+0], qfh[kc], rl[0], rl[1]);
                mma16816(s[2*ntp+1], qfh[kc], rl[2], rl[3]);
            }
        }

        const int r0 = qbase + wrow + group;
        const int r1 = r0 + 8;
        const bool needmask = (kt * 64 + 63) > (qbase + wrow);
        #pragma unroll
        for (int ni = 0; ni < 8; ni++) {
            #pragma unroll
            for (int f = 0; f < 4; f++) s[ni][f] *= SC2;
            if (needmask) {
                const int col = kt * 64 + ni * 8 + t4 * 2;
                if (col > r0)     s[ni][0] = -1e30f;
                if (col + 1 > r0) s[ni][1] = -1e30f;
                if (col > r1)     s[ni][2] = -1e30f;
                if (col + 1 > r1) s[ni][3] = -1e30f;
            }
        }

        float rm0 = -INFINITY, rm1 = -INFINITY;
        #pragma unroll
        for (int ni = 0; ni < 8; ni++) {
            rm0 = fmaxf(rm0, fmaxf(s[ni][0], s[ni][1]));
            rm1 = fmaxf(rm1, fmaxf(s[ni][2], s[ni][3]));
        }
        rm0 = fmaxf(rm0, __shfl_xor_sync(0xffffffff, rm0, 1));
        rm0 = fmaxf(rm0, __shfl_xor_sync(0xffffffff, rm0, 2));
        rm1 = fmaxf(rm1, __shfl_xor_sync(0xffffffff, rm1, 1));
        rm1 = fmaxf(rm1, __shfl_xor_sync(0xffffffff, rm1, 2));

        const float nm0 = fmaxf(m0, rm0), nm1 = fmaxf(m1, rm1);
        const float al0 = exp2f(m0 - nm0), al1 = exp2f(m1 - nm1);
        l0 *= al0; l1 *= al1;
        m0 = nm0; m1 = nm1;
        #pragma unroll
        for (int ni = 0; ni < 8; ni++) {
            o[ni][0] *= al0; o[ni][1] *= al0;
            o[ni][2] *= al1; o[ni][3] *= al1;
        }

        uint32_t pf[8][2];
        float la0 = 0.f, la1 = 0.f;
        #pragma unroll
        for (int ni = 0; ni < 8; ni++) {
            __half2 t0 = __floats2half2_rn(fmaxf(s[ni][0] - m0, -60.f),
                                           fmaxf(s[ni][1] - m0, -60.f));
            __half2 t1 = __floats2half2_rn(fmaxf(s[ni][2] - m1, -60.f),
                                           fmaxf(s[ni][3] - m1, -60.f));
            uint32_t p0 = h2ex2(*(uint32_t*)&t0);
            uint32_t p1 = h2ex2(*(uint32_t*)&t1);
            pf[ni][0] = p0; pf[ni][1] = p1;
            float2 f0 = __half22float2(*(__half2*)&p0);
            float2 f1 = __half22float2(*(__half2*)&p1);
            la0 += f0.x + f0.y;
            la1 += f1.x + f1.y;
        }
        la0 += __shfl_xor_sync(0xffffffff, la0, 1);
        la0 += __shfl_xor_sync(0xffffffff, la0, 2);
        la1 += __shfl_xor_sync(0xffffffff, la1, 1);
        la1 += __shfl_xor_sync(0xffffffff, la1, 2);
        l0 += la0; l1 += la1;

        #pragma unroll
        for (int kc = 0; kc < 4; kc++) {
            uint32_t a[4] = { pf[2*kc][0], pf[2*kc][1], pf[2*kc+1][0], pf[2*kc+1][1] };
            #pragma unroll
            for (int ntp = 0; ntp < 4; ntp++) {
                uint32_t rh[4], rl[4];
                const int off = (kc * 16 + v_row) * ATS + ntp * 16 + v_col;
                ldsm4t(rh, pVh + off);
                ldsm4t(rl, pVl + off);
                mma16816(o[2*ntp+0], a, rh[0], rh[1]);
                mma16816(o[2*ntp+1], a, rh[2], rh[3]);
                mma16816(o[2*ntp+0], a, rl[0], rl[1]);
                mma16816(o[2*ntp+1], a, rl[2], rl[3]);
            }
        }
        __syncthreads();
    }

    const float il0 = 1.0f / l0, il1 = 1.0f / l1;
    const size_t gr0 = (tokb + qbase + wrow + group) * DD + hoff;
    const size_t gr1 = gr0 + 8 * DD;
    #pragma unroll
    for (int ni = 0; ni < 8; ni++) {
        const int col = ni * 8 + t4 * 2;
        float v0 = o[ni][0] * il0, v1 = o[ni][1] * il0;
        float v2 = o[ni][2] * il1, v3 = o[ni][3] * il1;
        __half h0 = __float2half_rn(v0), h1 = __float2half_rn(v1);
        __half h2c = __float2half_rn(v2), h3 = __float2half_rn(v3);
        *(__half2*)(Ohi + gr0 + col) = __halves2half2(h0, h1);
        *(__half2*)(Olo + gr0 + col) = __halves2half2(
            __float2half_rn(v0 - __half2float(h0)), __float2half_rn(v1 - __half2float(h1)));
        *(__half2*)(Ohi + gr1 + col) = __halves2half2(h2c, h3);
        *(__half2*)(Olo + gr1 + col) = __halves2half2(
            __float2half_rn(v2 - __half2float(h2c)), __float2half_rn(v3 - __half2float(h3)));
    }
}

// ---------------------------------------------------------------------------
// kernel_launch
// ---------------------------------------------------------------------------
extern "C" void kernel_launch(void* const* d_in, const int* in_sizes, int n_in,
                              void* d_out, int out_size)
{
    const float* x     = (const float*)d_in[0];
    const float* ln1_g = (const float*)d_in[2];
    const float* ln1_b = (const float*)d_in[3];
    const float* ln2_g = (const float*)d_in[4];
    const float* ln2_b = (const float*)d_in[5];
    const float* Wq    = (const float*)d_in[6];
    const float* Wk    = (const float*)d_in[7];
    const float* Wv    = (const float*)d_in[8];
    const float* Wo    = (const float*)d_in[9];
    const float* Wff1  = (const float*)d_in[10];
    const float* Wff2  = (const float*)d_in[11];
    float* out = (float*)d_out;

    unsigned char* base = nullptr;
    cudaGetSymbolAddress((void**)&base, g_scratch);
    size_t off = 0;
    auto carve = [&](size_t bytes) { void* p = base + off; off += bytes; return p; };

    __half* qkv_hi = (__half*)carve((size_t)3 * SEG * 2);   // q | k | v (hi)
    __half* qkv_lo = (__half*)carve((size_t)3 * SEG * 2);
    __half* h_hi   = (__half*)carve((size_t)SEG * 2);
    __half* h_lo   = (__half*)carve((size_t)SEG * 2);
    __half* att_hi = (__half*)carve((size_t)SEG * 2);
    __half* att_lo = (__half*)carve((size_t)SEG * 2);
    __half* ff_hi  = (__half*)carve((size_t)ROWS * FFD * 2);
    __half* ff_lo  = (__half*)carve((size_t)ROWS * FFD * 2);
    __half* Wqkv_h = (__half*)carve((size_t)3 * DD * DD * 2);  // Wq|Wk|Wv contiguous
    __half* Wo_h   = (__half*)carve((size_t)DD * DD * 2);      // right after (w2h_attn dst)
    __half* Wff_h  = (__half*)carve((size_t)2 * FFD * DD * 2); // Wff1|Wff2 contiguous

    __half* Wf1_h = Wff_h;
    __half* Wf2_h = Wff_h + (size_t)FFD * DD;

    cudaFuncSetAttribute(gemm_f16<1>, cudaFuncAttributeMaxDynamicSharedMemorySize, (int)GSMEM);
    cudaFuncSetAttribute(gemm_f16<2>, cudaFuncAttributeMaxDynamicSharedMemorySize, (int)GSMEM);
    cudaFuncSetAttribute(gemm_f16<3>, cudaFuncAttributeMaxDynamicSharedMemorySize, (int)GSMEM);
    cudaFuncSetAttribute(gemm_f16<5>, cudaFuncAttributeMaxDynamicSharedMemorySize, (int)GSMEM);
    cudaFuncSetAttribute(attn_tc, cudaFuncAttributeMaxDynamicSharedMemorySize, (int)ASMEM);

    // launches ordered so ncu -s 5 captures launch #6 = Wo GEMM
    w2h_attn<<<4 * DD * DD / 1024, 256>>>(Wq, Wk, Wv, Wo, Wqkv_h);   // writes Wqkv_h + Wo_h
    w2h_ff<<<2 * FFD * DD / 1024, 256>>>(Wff1, Wff2, Wff_h);

    ln_split_kernel<<<ROWS, 256>>>(x, ln1_g, ln1_b, h_hi, h_lo);

    // fused QKV: N = 3072, segmented epilogue -> qkv_hi/qkv_lo
    gemm_f16<5><<<dim3(3 * DD / GN, ROWS / GM), 256, GSMEM>>>(
        h_hi, h_lo, Wqkv_h, nullptr, nullptr, qkv_hi, qkv_lo, ROWS, 3 * DD, DD);

    attn_tc<<<dim3(TT / 128, BB * HH), 256, ASMEM>>>(
        qkv_hi, qkv_lo, qkv_hi + SEG, qkv_lo + SEG, qkv_hi + 2 * SEG, qkv_lo + 2 * SEG,
        att_hi, att_lo);

    gemm_f16<1><<<dim3(DD / GN, ROWS / GM), 256, GSMEM>>>(
        att_hi, att_lo, Wo_h, out, x, nullptr, nullptr, ROWS, DD, DD);

    ln_split_kernel<<<ROWS, 256>>>(out, ln2_g, ln2_b, h_hi, h_lo);

    gemm_f16<2><<<dim3(FFD / GN, ROWS / GM), 256, GSMEM>>>(
        h_hi, h_lo, Wf1_h, nullptr, nullptr, ff_hi, ff_lo, ROWS, FFD, DD);

    gemm_f16<3><<<dim3(DD / GN, ROWS / GM), 256, GSMEM>>>(
        ff_hi, ff_lo, Wf2_h, out, nullptr, nullptr, nullptr, ROWS, DD, FFD);
}

// round 7
// speedup vs baseline: 4.7379x; 1.1529x over previous
#include <cuda_runtime.h>
#include <cuda_fp16.h>
#include <math.h>
#include <stdint.h>

// Problem constants
#define BB   2
#define TT   2048
#define DD   1024
#define HH   16
#define DHH  64
#define FFD  4096
#define ROWS (BB*TT)          // 4096
#define SEG  (ROWS * DD)      // 4194304 elements
#define EPSF 1e-5f

__device__ __align__(256) unsigned char g_scratch[190u * 1024u * 1024u];

// ---------------------------------------------------------------------------
// helpers
// ---------------------------------------------------------------------------
__device__ __forceinline__ uint32_t smem_u32(const void* p) {
    uint32_t a;
    asm("{ .reg .u64 t; cvta.to.shared.u64 t, %1; cvt.u32.u64 %0, t; }" : "=r"(a) : "l"(p));
    return a;
}
__device__ __forceinline__ uint32_t sw128(uint32_t bo) {
    return bo ^ ((bo >> 3) & 0x70);
}
__device__ __forceinline__ void cp_async16(uint32_t smem_dst, const void* gmem_src) {
    asm volatile("cp.async.cg.shared.global [%0], [%1], 16;\n" :: "r"(smem_dst), "l"(gmem_src));
}
__device__ __forceinline__ void cp_async16p(void* smem_dst, const void* gmem_src) {
    uint32_t s = smem_u32(smem_dst);
    asm volatile("cp.async.cg.shared.global [%0], [%1], 16;\n" :: "r"(s), "l"(gmem_src));
}
__device__ __forceinline__ void ldsm4a(uint32_t* r, uint32_t a) {
    asm volatile("ldmatrix.sync.aligned.m8n8.x4.shared.b16 {%0,%1,%2,%3}, [%4];"
        : "=r"(r[0]), "=r"(r[1]), "=r"(r[2]), "=r"(r[3]) : "r"(a));
}
__device__ __forceinline__ void ldsm4(uint32_t* r, const __half* p) {
    ldsm4a(r, smem_u32(p));
}
__device__ __forceinline__ void ldsm4t(uint32_t* r, const __half* p) {
    uint32_t a = smem_u32(p);
    asm volatile("ldmatrix.sync.aligned.m8n8.x4.trans.shared.b16 {%0,%1,%2,%3}, [%4];"
        : "=r"(r[0]), "=r"(r[1]), "=r"(r[2]), "=r"(r[3]) : "r"(a));
}
__device__ __forceinline__ void mma16816(float* c, const uint32_t* a, uint32_t b0, uint32_t b1) {
    asm volatile(
        "mma.sync.aligned.m16n8k16.row.col.f32.f16.f16.f32 "
        "{%0,%1,%2,%3}, {%4,%5,%6,%7}, {%8,%9}, {%0,%1,%2,%3};"
        : "+f"(c[0]), "+f"(c[1]), "+f"(c[2]), "+f"(c[3])
        : "r"(a[0]), "r"(a[1]), "r"(a[2]), "r"(a[3]), "r"(b0), "r"(b1));
}
__device__ __forceinline__ uint32_t h2ex2(uint32_t a) {
    uint32_t d;
    asm("ex2.approx.f16x2 %0, %1;" : "=r"(d) : "r"(a));
    return d;
}

// ---------------------------------------------------------------------------
// weight conversion
// ---------------------------------------------------------------------------
__global__ __launch_bounds__(256) void w2h_attn(
    const float* __restrict__ s0, const float* __restrict__ s1,
    const float* __restrict__ s2, const float* __restrict__ s3,
    __half* __restrict__ dst)
{
    const size_t idx = ((size_t)blockIdx.x * 256 + threadIdx.x) * 4;
    const int seg = (int)(idx >> 20);
    const float* s = (seg == 0) ? s0 : (seg == 1) ? s1 : (seg == 2) ? s2 : s3;
    float4 v = *(const float4*)(s + (idx & 0xFFFFF));
    *(__half2*)(dst + idx)     = __floats2half2_rn(v.x, v.y);
    *(__half2*)(dst + idx + 2) = __floats2half2_rn(v.z, v.w);
}
__global__ __launch_bounds__(256) void w2h_ff(
    const float* __restrict__ s0, const float* __restrict__ s1,
    __half* __restrict__ dst)
{
    const size_t idx = ((size_t)blockIdx.x * 256 + threadIdx.x) * 4;
    const int seg = (int)(idx >> 22);
    const float* s = (seg == 0) ? s0 : s1;
    float4 v = *(const float4*)(s + (idx & 0x3FFFFF));
    *(__half2*)(dst + idx)     = __floats2half2_rn(v.x, v.y);
    *(__half2*)(dst + idx + 2) = __floats2half2_rn(v.z, v.w);
}

// ---------------------------------------------------------------------------
// LayerNorm -> split hi/lo fp16
// ---------------------------------------------------------------------------
__global__ __launch_bounds__(256) void ln_split_kernel(
    const float* __restrict__ x, const float* __restrict__ g,
    const float* __restrict__ b, __half* __restrict__ ohi, __half* __restrict__ olo)
{
    const int row = blockIdx.x;
    const int tid = threadIdx.x;
    const float* xr = x + (size_t)row * DD;

    float4 v = *(const float4*)(xr + tid * 4);
    float s  = v.x + v.y + v.z + v.w;
    float ss = v.x * v.x + v.y * v.y + v.z * v.z + v.w * v.w;

    #pragma unroll
    for (int off = 16; off > 0; off >>= 1) {
        s  += __shfl_xor_sync(0xffffffff, s,  off);
        ss += __shfl_xor_sync(0xffffffff, ss, off);
    }
    __shared__ float sbuf[8], ssbuf[8];
    const int warp = tid >> 5, lane = tid & 31;
    if (lane == 0) { sbuf[warp] = s; ssbuf[warp] = ss; }
    __syncthreads();
    float S = 0.f, SS = 0.f;
    #pragma unroll
    for (int i = 0; i < 8; i++) { S += sbuf[i]; SS += ssbuf[i]; }

    const float mu  = S * (1.0f / DD);
    const float var = SS * (1.0f / DD) - mu * mu;
    const float rs  = rsqrtf(var + EPSF);

    float4 gg = *(const float4*)(g + tid * 4);
    float4 bb = *(const float4*)(b + tid * 4);
    float y0 = (v.x - mu) * rs * gg.x + bb.x;
    float y1 = (v.y - mu) * rs * gg.y + bb.y;
    float y2 = (v.z - mu) * rs * gg.z + bb.z;
    float y3 = (v.w - mu) * rs * gg.w + bb.w;

    __half h0 = __float2half_rn(y0), h1 = __float2half_rn(y1);
    __half h2 = __float2half_rn(y2), h3 = __float2half_rn(y3);
    const size_t base = (size_t)row * DD + tid * 4;
    *(__half2*)(ohi + base)     = __halves2half2(h0, h1);
    *(__half2*)(ohi + base + 2) = __halves2half2(h2, h3);
    *(__half2*)(olo + base)     = __halves2half2(
        __float2half_rn(y0 - __half2float(h0)), __float2half_rn(y1 - __half2float(h1)));
    *(__half2*)(olo + base + 2) = __halves2half2(
        __float2half_rn(y2 - __half2float(h2)), __float2half_rn(y3 - __half2float(h3)));
}

// ---------------------------------------------------------------------------
// fp16 split-A GEMM: C[M,N] = (A_hi+A_lo)[M,K] @ W[N,K]^T
// 128x128 tile, BK=64 halves (128B rows, XOR-swizzled), 2-stage cp.async,
// ONE __syncthreads per k64 iteration. 8 warps (2x4), 64x32 per warp.
// EPI: 1 C=acc+R(f32), 2 split(gelu)->Ohi/Olo, 3 C+=acc, 5 segmented split
// ---------------------------------------------------------------------------
#define GM 128
#define GN 128
#define GK 64
#define TILE_B 16384u                  // one 128x128B tile
#define STAGE_B (3u * TILE_B)          // Ah, Al, W
#define GSMEM (2u * STAGE_B)           // 98304 B

template<int EPI>
__global__ __launch_bounds__(256) void gemm_f16(
    const __half* __restrict__ Ah, const __half* __restrict__ Al,
    const __half* __restrict__ Wh, float* __restrict__ C,
    const float* __restrict__ R, __half* __restrict__ Ohi, __half* __restrict__ Olo,
    int M, int N, int K)
{
    extern __shared__ unsigned char smraw[];
    const uint32_t smb = smem_u32(smraw);

    const int tid   = threadIdx.x;
    const int lane  = tid & 31;
    const int warp  = tid >> 5;
    const int wm    = (warp >> 2) * 64;
    const int wn    = (warp & 3) * 32;
    const int group = lane >> 2;
    const int t4    = lane & 3;

    const int bm = blockIdx.y * GM;
    const int bn = blockIdx.x * GN;

    const int a_row = (lane & 7) + ((lane >> 3) & 1) * 8;
    const int a_k   = (lane >> 4) * 8;
    const int b_row = (lane & 7) + ((lane >> 4) & 1) * 8;
    const int b_k   = ((lane >> 3) & 1) * 8;

    float c[4][4][4];
    #pragma unroll
    for (int mi = 0; mi < 4; mi++)
        #pragma unroll
        for (int ni = 0; ni < 4; ni++)
            #pragma unroll
            for (int f = 0; f < 4; f++) c[mi][ni][f] = 0.f;

    const int KT = K / GK;

    // stage loader: 3 tiles x 1024 16B-chunks / 256 threads = 12 per thread
    #define STAGE_LOAD(st, k0)                                                      \
    {                                                                               \
        const uint32_t sb = smb + (st) * STAGE_B;                                   \
        _Pragma("unroll")                                                           \
        for (int i = 0; i < 12; i++) {                                              \
            const int id  = (i & 3) * 256 + tid;                                    \
            const int row = id >> 3;                                                \
            const int kq  = id & 7;                                                 \
            const uint32_t bo = row * 128 + kq * 16;                                \
            uint32_t dst; const __half* src; size_t gr;                             \
            if (i < 4)      { dst = sb + sw128(bo);                src = Ah; gr = (size_t)(bm + row) * K; } \
            else if (i < 8) { dst = sb + TILE_B + sw128(bo);       src = Al; gr = (size_t)(bm + row) * K; } \
            else            { dst = sb + 2 * TILE_B + sw128(bo);   src = Wh; gr = (size_t)(bn + row) * K; } \
            cp_async16(dst, src + gr + (k0) + kq * 8);                              \
        }                                                                           \
        asm volatile("cp.async.commit_group;\n");                                   \
    }

    STAGE_LOAD(0, 0)

    for (int kt = 0; kt < KT; kt++) {
        asm volatile("cp.async.wait_group 0;\n");
        __syncthreads();                       // data visible + prev stage free
        if (kt + 1 < KT) STAGE_LOAD((kt + 1) & 1, (kt + 1) * GK)

        const uint32_t sb = smb + (kt & 1) * STAGE_B;
        #pragma unroll
        for (int ks = 0; ks < 4; ks++) {
            uint32_t bf[4][2];
            #pragma unroll
            for (int ng = 0; ng < 2; ng++) {
                uint32_t r[4];
                ldsm4a(r, sb + 2 * TILE_B +
                       sw128((wn + ng * 16 + b_row) * 128 + (ks * 16 + b_k) * 2));
                bf[2 * ng + 0][0] = r[0]; bf[2 * ng + 0][1] = r[1];
                bf[2 * ng + 1][0] = r[2]; bf[2 * ng + 1][1] = r[3];
            }
            #pragma unroll
            for (int mi = 0; mi < 4; mi++) {
                uint32_t ah[4], al[4];
                const uint32_t bo = (wm + mi * 16 + a_row) * 128 + (ks * 16 + a_k) * 2;
                ldsm4a(ah, sb + sw128(bo));
                ldsm4a(al, sb + TILE_B + sw128(bo));
                #pragma unroll
                for (int ni = 0; ni < 4; ni++) {
                    mma16816(c[mi][ni], ah, bf[ni][0], bf[ni][1]);
                    mma16816(c[mi][ni], al, bf[ni][0], bf[ni][1]);
                }
            }
        }
    }

    // epilogue
    #pragma unroll
    for (int mi = 0; mi < 4; mi++) {
        #pragma unroll
        for (int hf = 0; hf < 2; hf++) {
            const int row = bm + wm + mi * 16 + group + hf * 8;
            #pragma unroll
            for (int ni = 0; ni < 4; ni++) {
                const int col = bn + wn + ni * 8 + t4 * 2;
                float v0 = c[mi][ni][hf * 2 + 0];
                float v1 = c[mi][ni][hf * 2 + 1];
                if (EPI == 1) {
                    float2 rr = *(const float2*)(R + (size_t)row * N + col);
                    float2 o; o.x = v0 + rr.x; o.y = v1 + rr.y;
                    *(float2*)(C + (size_t)row * N + col) = o;
                } else if (EPI == 2) {
                    v0 = 0.5f * v0 * (1.0f + erff(v0 * 0.70710678118654752f));
                    v1 = 0.5f * v1 * (1.0f + erff(v1 * 0.70710678118654752f));
                    __half h0 = __float2half_rn(v0), h1 = __float2half_rn(v1);
                    *(__half2*)(Ohi + (size_t)row * N + col) = __halves2half2(h0, h1);
                    *(__half2*)(Olo + (size_t)row * N + col) = __halves2half2(
                        __float2half_rn(v0 - __half2float(h0)),
                        __float2half_rn(v1 - __half2float(h1)));
                } else if (EPI == 5) {
                    const int seg = col >> 10;
                    const int lc  = col & 1023;
                    const size_t di = ((size_t)seg * ROWS + row) * DD + lc;
                    __half h0 = __float2half_rn(v0), h1 = __float2half_rn(v1);
                    *(__half2*)(Ohi + di) = __halves2half2(h0, h1);
                    *(__half2*)(Olo + di) = __halves2half2(
                        __float2half_rn(v0 - __half2float(h0)),
                        __float2half_rn(v1 - __half2float(h1)));
                } else {  // EPI == 3
                    float2 cc = *(const float2*)(C + (size_t)row * N + col);
                    float2 o; o.x = v0 + cc.x; o.y = v1 + cc.y;
                    *(float2*)(C + (size_t)row * N + col) = o;
                }
            }
        }
    }
}

// ---------------------------------------------------------------------------
// Tensor-core causal flash attention, single sync per K-tile.
// 256 thr, 8 warps x 16 q-rows; 64-key tiles double-buffered;
// Q parked in stage-1 overlay.
// ---------------------------------------------------------------------------
#define ATS 72
#define QBUF (128 * ATS)
#define KVT  (64 * ATS)
#define KVSTG (4 * KVT)
#define ASMEM (2u * KVSTG * sizeof(__half))

__global__ __launch_bounds__(256) void attn_tc(
    const __half* __restrict__ Qh, const __half* __restrict__ Ql,
    const __half* __restrict__ Kh, const __half* __restrict__ Kl,
    const __half* __restrict__ Vh, const __half* __restrict__ Vl,
    __half* __restrict__ Ohi, __half* __restrict__ Olo)
{
    extern __shared__ __half sm[];
    __half* sKV = sm;
    __half* sQh = sm + KVSTG;     // overlay on stage 1
    __half* sQl = sQh + QBUF;

    const int tid  = threadIdx.x;
    const int lane = tid & 31;
    const int warp = tid >> 5;
    const int wrow = warp * 16;
    const int group = lane >> 2;
    const int t4    = lane & 3;

    const int qtile = gridDim.x - 1 - blockIdx.x;
    const int bh = blockIdx.y;
    const int b = bh >> 4, h = bh & 15;
    const int qbase = qtile * 128;
    const int hoff  = h * DHH;
    const size_t tokb = (size_t)b * TT;

    const int a_row = (lane & 7) + ((lane >> 3) & 1) * 8;
    const int a_k   = (lane >> 4) * 8;
    const int b_row = (lane & 7) + ((lane >> 4) & 1) * 8;
    const int b_k   = ((lane >> 3) & 1) * 8;
    const int v_row = (lane & 7) + ((lane >> 3) & 1) * 8;
    const int v_col = (lane >> 4) * 8;

    // group 0: Q
    #pragma unroll
    for (int i = 0; i < 8; i++) {
        const int buf = i >> 2;
        const int within = (i & 3) * 256 + tid;
        const int row = within >> 3;
        const int c8  = (within & 7) * 8;
        const __half* src = (buf == 0 ? Qh : Ql) + (tokb + qbase + row) * DD + hoff + c8;
        cp_async16p((buf == 0 ? sQh : sQl) + row * ATS + c8, src);
    }
    asm volatile("cp.async.commit_group;\n");

    #define KV_LOAD(st, key0)                                                        \
    {                                                                                \
        _Pragma("unroll")                                                            \
        for (int i = 0; i < 8; i++) {                                                \
            const int tile = i >> 1;                                                 \
            const int row  = (i & 1) * 32 + (tid >> 3);                              \
            const int c8   = (tid & 7) * 8;                                          \
            const __half* src = (tile == 0 ? Kh : tile == 1 ? Kl :                   \
                                 tile == 2 ? Vh : Vl)                                \
                                + (tokb + (key0) + row) * DD + hoff + c8;            \
            cp_async16p(&sKV[(st) * KVSTG + tile * KVT + row * ATS + c8], src);      \
        }                                                                            \
        asm volatile("cp.async.commit_group;\n");                                    \
    }

    KV_LOAD(0, 0)                                // group 1
    asm volatile("cp.async.wait_group 1;\n");    // Q done
    __syncthreads();

    uint32_t qfh[4][4], qfl[4][4];
    #pragma unroll
    for (int kc = 0; kc < 4; kc++) {
        const int off = (wrow + a_row) * ATS + kc * 16 + a_k;
        ldsm4(qfh[kc], &sQh[off]);
        ldsm4(qfl[kc], &sQl[off]);
    }

    float o[8][4];
    #pragma unroll
    for (int ni = 0; ni < 8; ni++)
        #pragma unroll
        for (int f = 0; f < 4; f++) o[ni][f] = 0.f;
    float m0 = -INFINITY, m1 = -INFINITY, l0 = 0.f, l1 = 0.f;

    const float SC2 = 0.125f * 1.4426950408889634f;
    const int nkt = 2 * qtile + 2;

    for (int kt = 0; kt < nkt; kt++) {
        const int st = kt & 1;
        asm volatile("cp.async.wait_group 0;\n");   // kv(kt) done
        __syncthreads();   // visibility + Q-frag reads + prev-stage reuse
        if (kt + 1 < nkt) KV_LOAD(st ^ 1, (kt + 1) * 64)

        const __half* pKh = &sKV[st * KVSTG + 0 * KVT];
        const __half* pKl = &sKV[st * KVSTG + 1 * KVT];
        const __half* pVh = &sKV[st * KVSTG + 2 * KVT];
        const __half* pVl = &sKV[st * KVSTG + 3 * KVT];

        float s[8][4];
        #pragma unroll
        for (int ni = 0; ni < 8; ni++)
            #pragma unroll
            for (int f = 0; f < 4; f++) s[ni][f] = 0.f;

        #pragma unroll
        for (int kc = 0; kc < 4; kc++) {
            #pragma unroll
            for (int ntp = 0; ntp < 4; ntp++) {
                uint32_t rh[4], rl[4];
                const int off = (ntp * 16 + b_row) * ATS + kc * 16 + b_k;
                ldsm4(rh, pKh + off);
                ldsm4(rl, pKl + off);
                mma16816(s[2*ntp+0], qfh[kc], rh[0], rh[1]);
                mma16816(s[2*ntp+1], qfh[kc], rh[2], rh[3]);
                mma16816(s[2*ntp+0], qfl[kc], rh[0], rh[1]);
                mma16816(s[2*ntp+1], qfl[kc], rh[2], rh[3]);
                mma16816(s[2*ntp+0], qfh[kc], rl[0], rl[1]);
                mma16816(s[2*ntp+1], qfh[kc], rl[2], rl[3]);
            }
        }

        const int r0 = qbase + wrow + group;
        const int r1 = r0 + 8;
        const bool needmask = (kt * 64 + 63) > (qbase + wrow);
        #pragma unroll
        for (int ni = 0; ni < 8; ni++) {
            #pragma unroll
            for (int f = 0; f < 4; f++) s[ni][f] *= SC2;
            if (needmask) {
                const int col = kt * 64 + ni * 8 + t4 * 2;
                if (col > r0)     s[ni][0] = -1e30f;
                if (col + 1 > r0) s[ni][1] = -1e30f;
                if (col > r1)     s[ni][2] = -1e30f;
                if (col + 1 > r1) s[ni][3] = -1e30f;
            }
        }

        float rm0 = -INFINITY, rm1 = -INFINITY;
        #pragma unroll
        for (int ni = 0; ni < 8; ni++) {
            rm0 = fmaxf(rm0, fmaxf(s[ni][0], s[ni][1]));
            rm1 = fmaxf(rm1, fmaxf(s[ni][2], s[ni][3]));
        }
        rm0 = fmaxf(rm0, __shfl_xor_sync(0xffffffff, rm0, 1));
        rm0 = fmaxf(rm0, __shfl_xor_sync(0xffffffff, rm0, 2));
        rm1 = fmaxf(rm1, __shfl_xor_sync(0xffffffff, rm1, 1));
        rm1 = fmaxf(rm1, __shfl_xor_sync(0xffffffff, rm1, 2));

        const float nm0 = fmaxf(m0, rm0), nm1 = fmaxf(m1, rm1);
        const float al0 = exp2f(m0 - nm0), al1 = exp2f(m1 - nm1);
        l0 *= al0; l1 *= al1;
        m0 = nm0; m1 = nm1;
        #pragma unroll
        for (int ni = 0; ni < 8; ni++) {
            o[ni][0] *= al0; o[ni][1] *= al0;
            o[ni][2] *= al1; o[ni][3] *= al1;
        }

        uint32_t pf[8][2];
        float la0 = 0.f, la1 = 0.f;
        #pragma unroll
        for (int ni = 0; ni < 8; ni++) {
            __half2 t0 = __floats2half2_rn(fmaxf(s[ni][0] - m0, -60.f),
                                           fmaxf(s[ni][1] - m0, -60.f));
            __half2 t1 = __floats2half2_rn(fmaxf(s[ni][2] - m1, -60.f),
                                           fmaxf(s[ni][3] - m1, -60.f));
            uint32_t p0 = h2ex2(*(uint32_t*)&t0);
            uint32_t p1 = h2ex2(*(uint32_t*)&t1);
            pf[ni][0] = p0; pf[ni][1] = p1;
            float2 f0 = __half22float2(*(__half2*)&p0);
            float2 f1 = __half22float2(*(__half2*)&p1);
            la0 += f0.x + f0.y;
            la1 += f1.x + f1.y;
        }
        la0 += __shfl_xor_sync(0xffffffff, la0, 1);
        la0 += __shfl_xor_sync(0xffffffff, la0, 2);
        la1 += __shfl_xor_sync(0xffffffff, la1, 1);
        la1 += __shfl_xor_sync(0xffffffff, la1, 2);
        l0 += la0; l1 += la1;

        #pragma unroll
        for (int kc = 0; kc < 4; kc++) {
            uint32_t a[4] = { pf[2*kc][0], pf[2*kc][1], pf[2*kc+1][0], pf[2*kc+1][1] };
            #pragma unroll
            for (int ntp = 0; ntp < 4; ntp++) {
                uint32_t rh[4], rl[4];
                const int off = (kc * 16 + v_row) * ATS + ntp * 16 + v_col;
                ldsm4t(rh, pVh + off);
                ldsm4t(rl, pVl + off);
                mma16816(o[2*ntp+0], a, rh[0], rh[1]);
                mma16816(o[2*ntp+1], a, rh[2], rh[3]);
                mma16816(o[2*ntp+0], a, rl[0], rl[1]);
                mma16816(o[2*ntp+1], a, rl[2], rl[3]);
            }
        }
    }

    const float il0 = 1.0f / l0, il1 = 1.0f / l1;
    const size_t gr0 = (tokb + qbase + wrow + group) * DD + hoff;
    const size_t gr1 = gr0 + 8 * DD;
    #pragma unroll
    for (int ni = 0; ni < 8; ni++) {
        const int col = ni * 8 + t4 * 2;
        float v0 = o[ni][0] * il0, v1 = o[ni][1] * il0;
        float v2 = o[ni][2] * il1, v3 = o[ni][3] * il1;
        __half h0 = __float2half_rn(v0), h1 = __float2half_rn(v1);
        __half h2c = __float2half_rn(v2), h3 = __float2half_rn(v3);
        *(__half2*)(Ohi + gr0 + col) = __halves2half2(h0, h1);
        *(__half2*)(Olo + gr0 + col) = __halves2half2(
            __float2half_rn(v0 - __half2float(h0)), __float2half_rn(v1 - __half2float(h1)));
        *(__half2*)(Ohi + gr1 + col) = __halves2half2(h2c, h3);
        *(__half2*)(Olo + gr1 + col) = __halves2half2(
            __float2half_rn(v2 - __half2float(h2c)), __float2half_rn(v3 - __half2float(h3)));
    }
}

// ---------------------------------------------------------------------------
// kernel_launch
// ---------------------------------------------------------------------------
extern "C" void kernel_launch(void* const* d_in, const int* in_sizes, int n_in,
                              void* d_out, int out_size)
{
    const float* x     = (const float*)d_in[0];
    const float* ln1_g = (const float*)d_in[2];
    const float* ln1_b = (const float*)d_in[3];
    const float* ln2_g = (const float*)d_in[4];
    const float* ln2_b = (const float*)d_in[5];
    const float* Wq    = (const float*)d_in[6];
    const float* Wk    = (const float*)d_in[7];
    const float* Wv    = (const float*)d_in[8];
    const float* Wo    = (const float*)d_in[9];
    const float* Wff1  = (const float*)d_in[10];
    const float* Wff2  = (const float*)d_in[11];
    float* out = (float*)d_out;

    unsigned char* base = nullptr;
    cudaGetSymbolAddress((void**)&base, g_scratch);
    size_t off = 0;
    auto carve = [&](size_t bytes) { void* p = base + off; off += bytes; return p; };

    __half* qkv_hi = (__half*)carve((size_t)3 * SEG * 2);
    __half* qkv_lo = (__half*)carve((size_t)3 * SEG * 2);
    __half* h_hi   = (__half*)carve((size_t)SEG * 2);
    __half* h_lo   = (__half*)carve((size_t)SEG * 2);
    __half* att_hi = (__half*)carve((size_t)SEG * 2);
    __half* att_lo = (__half*)carve((size_t)SEG * 2);
    __half* ff_hi  = (__half*)carve((size_t)ROWS * FFD * 2);
    __half* ff_lo  = (__half*)carve((size_t)ROWS * FFD * 2);
    __half* Wqkv_h = (__half*)carve((size_t)3 * DD * DD * 2);
    __half* Wo_h   = (__half*)carve((size_t)DD * DD * 2);
    __half* Wff_h  = (__half*)carve((size_t)2 * FFD * DD * 2);

    __half* Wf1_h = Wff_h;
    __half* Wf2_h = Wff_h + (size_t)FFD * DD;

    cudaFuncSetAttribute(gemm_f16<1>, cudaFuncAttributeMaxDynamicSharedMemorySize, (int)GSMEM);
    cudaFuncSetAttribute(gemm_f16<2>, cudaFuncAttributeMaxDynamicSharedMemorySize, (int)GSMEM);
    cudaFuncSetAttribute(gemm_f16<3>, cudaFuncAttributeMaxDynamicSharedMemorySize, (int)GSMEM);
    cudaFuncSetAttribute(gemm_f16<5>, cudaFuncAttributeMaxDynamicSharedMemorySize, (int)GSMEM);
    cudaFuncSetAttribute(attn_tc, cudaFuncAttributeMaxDynamicSharedMemorySize, (int)ASMEM);

    // launches ordered so ncu -s 5 captures launch #6 = Wo GEMM
    w2h_attn<<<4 * DD * DD / 1024, 256>>>(Wq, Wk, Wv, Wo, Wqkv_h);
    w2h_ff<<<2 * FFD * DD / 1024, 256>>>(Wff1, Wff2, Wff_h);

    ln_split_kernel<<<ROWS, 256>>>(x, ln1_g, ln1_b, h_hi, h_lo);

    // fused QKV: N = 3072
    gemm_f16<5><<<dim3(3 * DD / GN, ROWS / GM), 256, GSMEM>>>(
        h_hi, h_lo, Wqkv_h, nullptr, nullptr, qkv_hi, qkv_lo, ROWS, 3 * DD, DD);

    attn_tc<<<dim3(TT / 128, BB * HH), 256, ASMEM>>>(
        qkv_hi, qkv_lo, qkv_hi + SEG, qkv_lo + SEG, qkv_hi + 2 * SEG, qkv_lo + 2 * SEG,
        att_hi, att_lo);

    gemm_f16<1><<<dim3(DD / GN, ROWS / GM), 256, GSMEM>>>(
        att_hi, att_lo, Wo_h, out, x, nullptr, nullptr, ROWS, DD, DD);

    ln_split_kernel<<<ROWS, 256>>>(out, ln2_g, ln2_b, h_hi, h_lo);

    gemm_f16<2><<<dim3(FFD / GN, ROWS / GM), 256, GSMEM>>>(
        h_hi, h_lo, Wf1_h, nullptr, nullptr, ff_hi, ff_lo, ROWS, FFD, DD);

    gemm_f16<3><<<dim3(DD / GN, ROWS / GM), 256, GSMEM>>>(
        ff_hi, ff_lo, Wf2_h, out, nullptr, nullptr, nullptr, ROWS, DD, FFD);
}

// round 8
// speedup vs baseline: 6.5765x; 1.3881x over previous
#include <cuda_runtime.h>
#include <cuda_fp16.h>
#include <math.h>
#include <stdint.h>

// Problem constants
#define BB   2
#define TT   2048
#define DD   1024
#define HH   16
#define DHH  64
#define FFD  4096
#define ROWS (BB*TT)          // 4096
#define SEG  (ROWS * DD)      // 4194304 elements
#define EPSF 1e-5f

__device__ __align__(256) unsigned char g_scratch[190u * 1024u * 1024u];

// ---------------------------------------------------------------------------
// helpers
// ---------------------------------------------------------------------------
__device__ __forceinline__ uint32_t smem_u32(const void* p) {
    uint32_t a;
    asm("{ .reg .u64 t; cvta.to.shared.u64 t, %1; cvt.u32.u64 %0, t; }" : "=r"(a) : "l"(p));
    return a;
}
__device__ __forceinline__ uint32_t sw128(uint32_t bo) {
    return bo ^ ((bo >> 3) & 0x70);
}
__device__ __forceinline__ void cp_async16(uint32_t smem_dst, const void* gmem_src) {
    asm volatile("cp.async.cg.shared.global [%0], [%1], 16;\n" :: "r"(smem_dst), "l"(gmem_src));
}
__device__ __forceinline__ void cp_async16p(void* smem_dst, const void* gmem_src) {
    uint32_t s = smem_u32(smem_dst);
    asm volatile("cp.async.cg.shared.global [%0], [%1], 16;\n" :: "r"(s), "l"(gmem_src));
}
__device__ __forceinline__ void ldsm4a(uint32_t* r, uint32_t a) {
    asm volatile("ldmatrix.sync.aligned.m8n8.x4.shared.b16 {%0,%1,%2,%3}, [%4];"
        : "=r"(r[0]), "=r"(r[1]), "=r"(r[2]), "=r"(r[3]) : "r"(a));
}
__device__ __forceinline__ void ldsm4(uint32_t* r, const __half* p) {
    ldsm4a(r, smem_u32(p));
}
__device__ __forceinline__ void ldsm4t(uint32_t* r, const __half* p) {
    uint32_t a = smem_u32(p);
    asm volatile("ldmatrix.sync.aligned.m8n8.x4.trans.shared.b16 {%0,%1,%2,%3}, [%4];"
        : "=r"(r[0]), "=r"(r[1]), "=r"(r[2]), "=r"(r[3]) : "r"(a));
}
__device__ __forceinline__ void mma16816(float* c, const uint32_t* a, uint32_t b0, uint32_t b1) {
    asm volatile(
        "mma.sync.aligned.m16n8k16.row.col.f32.f16.f16.f32 "
        "{%0,%1,%2,%3}, {%4,%5,%6,%7}, {%8,%9}, {%0,%1,%2,%3};"
        : "+f"(c[0]), "+f"(c[1]), "+f"(c[2]), "+f"(c[3])
        : "r"(a[0]), "r"(a[1]), "r"(a[2]), "r"(a[3]), "r"(b0), "r"(b1));
}
__device__ __forceinline__ uint32_t h2ex2(uint32_t a) {
    uint32_t d;
    asm("ex2.approx.f16x2 %0, %1;" : "=r"(d) : "r"(a));
    return d;
}

// ---------------------------------------------------------------------------
// weight conversion
// ---------------------------------------------------------------------------
__global__ __launch_bounds__(256) void w2h_attn(
    const float* __restrict__ s0, const float* __restrict__ s1,
    const float* __restrict__ s2, const float* __restrict__ s3,
    __half* __restrict__ dst)
{
    const size_t idx = ((size_t)blockIdx.x * 256 + threadIdx.x) * 4;
    const int seg = (int)(idx >> 20);
    const float* s = (seg == 0) ? s0 : (seg == 1) ? s1 : (seg == 2) ? s2 : s3;
    float4 v = *(const float4*)(s + (idx & 0xFFFFF));
    *(__half2*)(dst + idx)     = __floats2half2_rn(v.x, v.y);
    *(__half2*)(dst + idx + 2) = __floats2half2_rn(v.z, v.w);
}
__global__ __launch_bounds__(256) void w2h_ff(
    const float* __restrict__ s0, const float* __restrict__ s1,
    __half* __restrict__ dst)
{
    const size_t idx = ((size_t)blockIdx.x * 256 + threadIdx.x) * 4;
    const int seg = (int)(idx >> 22);
    const float* s = (seg == 0) ? s0 : s1;
    float4 v = *(const float4*)(s + (idx & 0x3FFFFF));
    *(__half2*)(dst + idx)     = __floats2half2_rn(v.x, v.y);
    *(__half2*)(dst + idx + 2) = __floats2half2_rn(v.z, v.w);
}

// ---------------------------------------------------------------------------
// LayerNorm -> split hi/lo fp16
// ---------------------------------------------------------------------------
__global__ __launch_bounds__(256) void ln_split_kernel(
    const float* __restrict__ x, const float* __restrict__ g,
    const float* __restrict__ b, __half* __restrict__ ohi, __half* __restrict__ olo)
{
    const int row = blockIdx.x;
    const int tid = threadIdx.x;
    const float* xr = x + (size_t)row * DD;

    float4 v = *(const float4*)(xr + tid * 4);
    float s  = v.x + v.y + v.z + v.w;
    float ss = v.x * v.x + v.y * v.y + v.z * v.z + v.w * v.w;

    #pragma unroll
    for (int off = 16; off > 0; off >>= 1) {
        s  += __shfl_xor_sync(0xffffffff, s,  off);
        ss += __shfl_xor_sync(0xffffffff, ss, off);
    }
    __shared__ float sbuf[8], ssbuf[8];
    const int warp = tid >> 5, lane = tid & 31;
    if (lane == 0) { sbuf[warp] = s; ssbuf[warp] = ss; }
    __syncthreads();
    float S = 0.f, SS = 0.f;
    #pragma unroll
    for (int i = 0; i < 8; i++) { S += sbuf[i]; SS += ssbuf[i]; }

    const float mu  = S * (1.0f / DD);
    const float var = SS * (1.0f / DD) - mu * mu;
    const float rs  = rsqrtf(var + EPSF);

    float4 gg = *(const float4*)(g + tid * 4);
    float4 bb = *(const float4*)(b + tid * 4);
    float y0 = (v.x - mu) * rs * gg.x + bb.x;
    float y1 = (v.y - mu) * rs * gg.y + bb.y;
    float y2 = (v.z - mu) * rs * gg.z + bb.z;
    float y3 = (v.w - mu) * rs * gg.w + bb.w;

    __half h0 = __float2half_rn(y0), h1 = __float2half_rn(y1);
    __half h2 = __float2half_rn(y2), h3 = __float2half_rn(y3);
    const size_t base = (size_t)row * DD + tid * 4;
    *(__half2*)(ohi + base)     = __halves2half2(h0, h1);
    *(__half2*)(ohi + base + 2) = __halves2half2(h2, h3);
    *(__half2*)(olo + base)     = __halves2half2(
        __float2half_rn(y0 - __half2float(h0)), __float2half_rn(y1 - __half2float(h1)));
    *(__half2*)(olo + base + 2) = __halves2half2(
        __float2half_rn(y2 - __half2float(h2)), __float2half_rn(y3 - __half2float(h3)));
}

// ---------------------------------------------------------------------------
// fp16 GEMM: C[M,N] = A[M,K] @ W[N,K]^T, A = Ah (+ Al if NLIMB==2)
// 128x128 tile, BK=64 (128B rows, XOR-swizzled), 2-stage cp.async,
// ONE __syncthreads per k64 iter. 8 warps (2x4), 64x32 per warp.
// EPI: 1 C=acc+R(f32), 2 gelu->Ohi, 3 C+=acc, 5 segmented split (QKV)
// ---------------------------------------------------------------------------
#define GM 128
#define GN 128
#define GK 64
#define TILE_B 16384u

template<int EPI, int NLIMB>
__global__ __launch_bounds__(256) void gemm_f16(
    const __half* __restrict__ Ah, const __half* __restrict__ Al,
    const __half* __restrict__ Wh, float* __restrict__ C,
    const float* __restrict__ R, __half* __restrict__ Ohi, __half* __restrict__ Olo,
    int M, int N, int K)
{
    extern __shared__ unsigned char smraw[];
    const uint32_t smb = smem_u32(smraw);

    constexpr int PL = NLIMB + 1;                 // planes per stage (A limbs + W)
    constexpr uint32_t STAGEB = PL * TILE_B;

    const int tid   = threadIdx.x;
    const int lane  = tid & 31;
    const int warp  = tid >> 5;
    const int wm    = (warp >> 2) * 64;
    const int wn    = (warp & 3) * 32;
    const int group = lane >> 2;
    const int t4    = lane & 3;

    const int bm = blockIdx.y * GM;
    const int bn = blockIdx.x * GN;

    const int a_row = (lane & 7) + ((lane >> 3) & 1) * 8;
    const int a_k   = (lane >> 4) * 8;
    const int b_row = (lane & 7) + ((lane >> 4) & 1) * 8;
    const int b_k   = ((lane >> 3) & 1) * 8;

    float c[4][4][4];
    #pragma unroll
    for (int mi = 0; mi < 4; mi++)
        #pragma unroll
        for (int ni = 0; ni < 4; ni++)
            #pragma unroll
            for (int f = 0; f < 4; f++) c[mi][ni][f] = 0.f;

    const int KT = K / GK;

    #define STAGE_LOAD(st, k0)                                                      \
    {                                                                               \
        const uint32_t sb_ = smb + (st) * STAGEB;                                   \
        _Pragma("unroll")                                                           \
        for (int i = 0; i < 4 * PL; i++) {                                          \
            const int pl  = i >> 2;                                                 \
            const int id  = (i & 3) * 256 + tid;                                    \
            const int row = id >> 3;                                                \
            const int kq  = id & 7;                                                 \
            const uint32_t bo = row * 128 + kq * 16;                                \
            const __half* src; size_t gr;                                           \
            if (pl == NLIMB)      { src = Wh; gr = (size_t)(bn + row) * K; }        \
            else if (pl == 0)     { src = Ah; gr = (size_t)(bm + row) * K; }        \
            else                  { src = Al; gr = (size_t)(bm + row) * K; }        \
            cp_async16(sb_ + pl * TILE_B + sw128(bo), src + gr + (k0) + kq * 8);    \
        }                                                                           \
        asm volatile("cp.async.commit_group;\n");                                   \
    }

    STAGE_LOAD(0, 0)

    for (int kt = 0; kt < KT; kt++) {
        asm volatile("cp.async.wait_group 0;\n");
        __syncthreads();                       // data visible + prev stage free
        if (kt + 1 < KT) STAGE_LOAD((kt + 1) & 1, (kt + 1) * GK)

        const uint32_t sb = smb + (kt & 1) * STAGEB;
        #pragma unroll
        for (int ks = 0; ks < 4; ks++) {
            uint32_t bf[4][2];
            #pragma unroll
            for (int ng = 0; ng < 2; ng++) {
                uint32_t r[4];
                ldsm4a(r, sb + NLIMB * TILE_B +
                       sw128((wn + ng * 16 + b_row) * 128 + (ks * 16 + b_k) * 2));
                bf[2 * ng + 0][0] = r[0]; bf[2 * ng + 0][1] = r[1];
                bf[2 * ng + 1][0] = r[2]; bf[2 * ng + 1][1] = r[3];
            }
            #pragma unroll
            for (int mi = 0; mi < 4; mi++) {
                uint32_t ah[4];
                const uint32_t bo = (wm + mi * 16 + a_row) * 128 + (ks * 16 + a_k) * 2;
                ldsm4a(ah, sb + sw128(bo));
                if (NLIMB == 2) {
                    uint32_t al[4];
                    ldsm4a(al, sb + TILE_B + sw128(bo));
                    #pragma unroll
                    for (int ni = 0; ni < 4; ni++) {
                        mma16816(c[mi][ni], ah, bf[ni][0], bf[ni][1]);
                        mma16816(c[mi][ni], al, bf[ni][0], bf[ni][1]);
                    }
                } else {
                    #pragma unroll
                    for (int ni = 0; ni < 4; ni++)
                        mma16816(c[mi][ni], ah, bf[ni][0], bf[ni][1]);
                }
            }
        }
    }

    // epilogue
    #pragma unroll
    for (int mi = 0; mi < 4; mi++) {
        #pragma unroll
        for (int hf = 0; hf < 2; hf++) {
            const int row = bm + wm + mi * 16 + group + hf * 8;
            #pragma unroll
            for (int ni = 0; ni < 4; ni++) {
                const int col = bn + wn + ni * 8 + t4 * 2;
                float v0 = c[mi][ni][hf * 2 + 0];
                float v1 = c[mi][ni][hf * 2 + 1];
                if (EPI == 1) {
                    float2 rr = *(const float2*)(R + (size_t)row * N + col);
                    float2 o; o.x = v0 + rr.x; o.y = v1 + rr.y;
                    *(float2*)(C + (size_t)row * N + col) = o;
                } else if (EPI == 2) {
                    v0 = 0.5f * v0 * (1.0f + erff(v0 * 0.70710678118654752f));
                    v1 = 0.5f * v1 * (1.0f + erff(v1 * 0.70710678118654752f));
                    *(__half2*)(Ohi + (size_t)row * N + col) =
                        __floats2half2_rn(v0, v1);
                } else if (EPI == 5) {
                    const int seg = col >> 10;
                    const int lc  = col & 1023;
                    const size_t di = ((size_t)seg * ROWS + row) * DD + lc;
                    __half h0 = __float2half_rn(v0), h1 = __float2half_rn(v1);
                    *(__half2*)(Ohi + di) = __halves2half2(h0, h1);
                    if (seg < 2) {   // V consumer never reads lo
                        *(__half2*)(Olo + di) = __halves2half2(
                            __float2half_rn(v0 - __half2float(h0)),
                            __float2half_rn(v1 - __half2float(h1)));
                    }
                } else {  // EPI == 3
                    float2 cc = *(const float2*)(C + (size_t)row * N + col);
                    float2 o; o.x = v0 + cc.x; o.y = v1 + cc.y;
                    *(float2*)(C + (size_t)row * N + col) = o;
                }
            }
        }
    }
}

// ---------------------------------------------------------------------------
// Tensor-core causal flash attention.
// 256 thr, 8 warps x 16 q-rows; 64-key tiles (Kh,Kl,Vh) double-buffered;
// S = QhKh + QlKh + QhKl; P@Vh only. Output: hi fp16 only.
// ---------------------------------------------------------------------------
#define ATS 72
#define QBUF (128 * ATS)
#define KVT  (64 * ATS)
#define KVSTG3 (3 * KVT)
#define ASMEM ((2u * KVSTG3 + 2u * QBUF) * sizeof(__half))   // 92160 B

__global__ __launch_bounds__(256) void attn_tc(
    const __half* __restrict__ Qh, const __half* __restrict__ Ql,
    const __half* __restrict__ Kh, const __half* __restrict__ Kl,
    const __half* __restrict__ Vh,
    __half* __restrict__ Ohi)
{
    extern __shared__ __half sm[];
    __half* sKV = sm;                  // [2][KVSTG3]
    __half* sQh = sm + 2 * KVSTG3;
    __half* sQl = sQh + QBUF;

    const int tid  = threadIdx.x;
    const int lane = tid & 31;
    const int warp = tid >> 5;
    const int wrow = warp * 16;
    const int group = lane >> 2;
    const int t4    = lane & 3;

    const int qtile = gridDim.x - 1 - blockIdx.x;   // long blocks first
    const int bh = blockIdx.y;
    const int b = bh >> 4, h = bh & 15;
    const int qbase = qtile * 128;
    const int hoff  = h * DHH;
    const size_t tokb = (size_t)b * TT;

    const int a_row = (lane & 7) + ((lane >> 3) & 1) * 8;
    const int a_k   = (lane >> 4) * 8;
    const int b_row = (lane & 7) + ((lane >> 4) & 1) * 8;
    const int b_k   = ((lane >> 3) & 1) * 8;
    const int v_row = (lane & 7) + ((lane >> 3) & 1) * 8;
    const int v_col = (lane >> 4) * 8;

    // group 0: Q (hi + lo)
    #pragma unroll
    for (int i = 0; i < 8; i++) {
        const int buf = i >> 2;
        const int within = (i & 3) * 256 + tid;
        const int row = within >> 3;
        const int c8  = (within & 7) * 8;
        const __half* src = (buf == 0 ? Qh : Ql) + (tokb + qbase + row) * DD + hoff + c8;
        cp_async16p((buf == 0 ? sQh : sQl) + row * ATS + c8, src);
    }
    asm volatile("cp.async.commit_group;\n");

    #define KV_LOAD(st, key0)                                                        \
    {                                                                                \
        _Pragma("unroll")                                                            \
        for (int i = 0; i < 6; i++) {                                                \
            const int tile = i >> 1;                                                 \
            const int row  = (i & 1) * 32 + (tid >> 3);                              \
            const int c8   = (tid & 7) * 8;                                          \
            const __half* src = (tile == 0 ? Kh : tile == 1 ? Kl : Vh)               \
                                + (tokb + (key0) + row) * DD + hoff + c8;            \
            cp_async16p(&sKV[(st) * KVSTG3 + tile * KVT + row * ATS + c8], src);     \
        }                                                                            \
        asm volatile("cp.async.commit_group;\n");                                    \
    }

    KV_LOAD(0, 0)                                // group 1
    asm volatile("cp.async.wait_group 1;\n");    // Q done
    __syncthreads();

    uint32_t qfh[4][4], qfl[4][4];
    #pragma unroll
    for (int kc = 0; kc < 4; kc++) {
        const int off = (wrow + a_row) * ATS + kc * 16 + a_k;
        ldsm4(qfh[kc], &sQh[off]);
        ldsm4(qfl[kc], &sQl[off]);
    }

    float o[8][4];
    #pragma unroll
    for (int ni = 0; ni < 8; ni++)
        #pragma unroll
        for (int f = 0; f < 4; f++) o[ni][f] = 0.f;
    float m0 = -INFINITY, m1 = -INFINITY, l0 = 0.f, l1 = 0.f;

    const float SC2 = 0.125f * 1.4426950408889634f;
    const int nkt = 2 * qtile + 2;

    for (int kt = 0; kt < nkt; kt++) {
        const int st = kt & 1;
        asm volatile("cp.async.wait_group 0;\n");   // kv(kt) done
        __syncthreads();
        if (kt + 1 < nkt) KV_LOAD(st ^ 1, (kt + 1) * 64)

        const __half* pKh = &sKV[st * KVSTG3 + 0 * KVT];
        const __half* pKl = &sKV[st * KVSTG3 + 1 * KVT];
        const __half* pVh = &sKV[st * KVSTG3 + 2 * KVT];

        float s[8][4];
        #pragma unroll
        for (int ni = 0; ni < 8; ni++)
            #pragma unroll
            for (int f = 0; f < 4; f++) s[ni][f] = 0.f;

        #pragma unroll
        for (int kc = 0; kc < 4; kc++) {
            #pragma unroll
            for (int ntp = 0; ntp < 4; ntp++) {
                uint32_t rh[4], rl[4];
                const int off = (ntp * 16 + b_row) * ATS + kc * 16 + b_k;
                ldsm4(rh, pKh + off);
                ldsm4(rl, pKl + off);
                mma16816(s[2*ntp+0], qfh[kc], rh[0], rh[1]);
                mma16816(s[2*ntp+1], qfh[kc], rh[2], rh[3]);
                mma16816(s[2*ntp+0], qfl[kc], rh[0], rh[1]);
                mma16816(s[2*ntp+1], qfl[kc], rh[2], rh[3]);
                mma16816(s[2*ntp+0], qfh[kc], rl[0], rl[1]);
                mma16816(s[2*ntp+1], qfh[kc], rl[2], rl[3]);
            }
        }

        const int r0 = qbase + wrow + group;
        const int r1 = r0 + 8;
        const bool needmask = (kt * 64 + 63) > (qbase + wrow);
        #pragma unroll
        for (int ni = 0; ni < 8; ni++) {
            #pragma unroll
            for (int f = 0; f < 4; f++) s[ni][f] *= SC2;
            if (needmask) {
                const int col = kt * 64 + ni * 8 + t4 * 2;
                if (col > r0)     s[ni][0] = -1e30f;
                if (col + 1 > r0) s[ni][1] = -1e30f;
                if (col > r1)     s[ni][2] = -1e30f;
                if (col + 1 > r1) s[ni][3] = -1e30f;
            }
        }

        float rm0 = -INFINITY, rm1 = -INFINITY;
        #pragma unroll
        for (int ni = 0; ni < 8; ni++) {
            rm0 = fmaxf(rm0, fmaxf(s[ni][0], s[ni][1]));
            rm1 = fmaxf(rm1, fmaxf(s[ni][2], s[ni][3]));
        }
        rm0 = fmaxf(rm0, __shfl_xor_sync(0xffffffff, rm0, 1));
        rm0 = fmaxf(rm0, __shfl_xor_sync(0xffffffff, rm0, 2));
        rm1 = fmaxf(rm1, __shfl_xor_sync(0xffffffff, rm1, 1));
        rm1 = fmaxf(rm1, __shfl_xor_sync(0xffffffff, rm1, 2));

        const float nm0 = fmaxf(m0, rm0), nm1 = fmaxf(m1, rm1);
        const float al0 = exp2f(m0 - nm0), al1 = exp2f(m1 - nm1);
        l0 *= al0; l1 *= al1;
        m0 = nm0; m1 = nm1;
        #pragma unroll
        for (int ni = 0; ni < 8; ni++) {
            o[ni][0] *= al0; o[ni][1] *= al0;
            o[ni][2] *= al1; o[ni][3] *= al1;
        }

        uint32_t pf[8][2];
        float la0 = 0.f, la1 = 0.f;
        #pragma unroll
        for (int ni = 0; ni < 8; ni++) {
            __half2 t0 = __floats2half2_rn(fmaxf(s[ni][0] - m0, -60.f),
                                           fmaxf(s[ni][1] - m0, -60.f));
            __half2 t1 = __floats2half2_rn(fmaxf(s[ni][2] - m1, -60.f),
                                           fmaxf(s[ni][3] - m1, -60.f));
            uint32_t p0 = h2ex2(*(uint32_t*)&t0);
            uint32_t p1 = h2ex2(*(uint32_t*)&t1);
            pf[ni][0] = p0; pf[ni][1] = p1;
            float2 f0 = __half22float2(*(__half2*)&p0);
            float2 f1 = __half22float2(*(__half2*)&p1);
            la0 += f0.x + f0.y;
            la1 += f1.x + f1.y;
        }
        la0 += __shfl_xor_sync(0xffffffff, la0, 1);
        la0 += __shfl_xor_sync(0xffffffff, la0, 2);
        la1 += __shfl_xor_sync(0xffffffff, la1, 1);
        la1 += __shfl_xor_sync(0xffffffff, la1, 2);
        l0 += la0; l1 += la1;

        #pragma unroll
        for (int kc = 0; kc < 4; kc++) {
            uint32_t a[4] = { pf[2*kc][0], pf[2*kc][1], pf[2*kc+1][0], pf[2*kc+1][1] };
            #pragma unroll
            for (int ntp = 0; ntp < 4; ntp++) {
                uint32_t rh[4];
                const int off = (kc * 16 + v_row) * ATS + ntp * 16 + v_col;
                ldsm4t(rh, pVh + off);
                mma16816(o[2*ntp+0], a, rh[0], rh[1]);
                mma16816(o[2*ntp+1], a, rh[2], rh[3]);
            }
        }
    }

    const float il0 = 1.0f / l0, il1 = 1.0f / l1;
    const size_t gr0 = (tokb + qbase + wrow + group) * DD + hoff;
    const size_t gr1 = gr0 + 8 * DD;
    #pragma unroll
    for (int ni = 0; ni < 8; ni++) {
        const int col = ni * 8 + t4 * 2;
        *(__half2*)(Ohi + gr0 + col) = __floats2half2_rn(o[ni][0] * il0, o[ni][1] * il0);
        *(__half2*)(Ohi + gr1 + col) = __floats2half2_rn(o[ni][2] * il1, o[ni][3] * il1);
    }
}

// ---------------------------------------------------------------------------
// kernel_launch
// ---------------------------------------------------------------------------
extern "C" void kernel_launch(void* const* d_in, const int* in_sizes, int n_in,
                              void* d_out, int out_size)
{
    const float* x     = (const float*)d_in[0];
    const float* ln1_g = (const float*)d_in[2];
    const float* ln1_b = (const float*)d_in[3];
    const float* ln2_g = (const float*)d_in[4];
    const float* ln2_b = (const float*)d_in[5];
    const float* Wq    = (const float*)d_in[6];
    const float* Wk    = (const float*)d_in[7];
    const float* Wv    = (const float*)d_in[8];
    const float* Wo    = (const float*)d_in[9];
    const float* Wff1  = (const float*)d_in[10];
    const float* Wff2  = (const float*)d_in[11];
    float* out = (float*)d_out;

    unsigned char* base = nullptr;
    cudaGetSymbolAddress((void**)&base, g_scratch);
    size_t off = 0;
    auto carve = [&](size_t bytes) { void* p = base + off; off += bytes; return p; };

    __half* qkv_hi = (__half*)carve((size_t)3 * SEG * 2);
    __half* qkv_lo = (__half*)carve((size_t)3 * SEG * 2);   // V segment unused
    __half* h_hi   = (__half*)carve((size_t)SEG * 2);
    __half* h_lo   = (__half*)carve((size_t)SEG * 2);
    __half* att_hi = (__half*)carve((size_t)SEG * 2);
    __half* ff_hi  = (__half*)carve((size_t)ROWS * FFD * 2);
    __half* Wqkv_h = (__half*)carve((size_t)3 * DD * DD * 2);
    __half* Wo_h   = (__half*)carve((size_t)DD * DD * 2);
    __half* Wff_h  = (__half*)carve((size_t)2 * FFD * DD * 2);

    __half* Wf1_h = Wff_h;
    __half* Wf2_h = Wff_h + (size_t)FFD * DD;

    const uint32_t SM2 = 2u * 3u * TILE_B;   // NLIMB=2 stages: 98304 B
    const uint32_t SM1 = 2u * 2u * TILE_B;   // NLIMB=1 stages: 65536 B
    cudaFuncSetAttribute((const void*)gemm_f16<5,2>, cudaFuncAttributeMaxDynamicSharedMemorySize, (int)SM2);
    cudaFuncSetAttribute((const void*)gemm_f16<1,1>, cudaFuncAttributeMaxDynamicSharedMemorySize, (int)SM1);
    cudaFuncSetAttribute((const void*)gemm_f16<2,1>, cudaFuncAttributeMaxDynamicSharedMemorySize, (int)SM1);
    cudaFuncSetAttribute((const void*)gemm_f16<3,1>, cudaFuncAttributeMaxDynamicSharedMemorySize, (int)SM1);
    cudaFuncSetAttribute((const void*)attn_tc, cudaFuncAttributeMaxDynamicSharedMemorySize, (int)ASMEM);

    // launches ordered so ncu -s 5 captures launch #6 = Wo GEMM
    w2h_attn<<<4 * DD * DD / 1024, 256>>>(Wq, Wk, Wv, Wo, Wqkv_h);
    w2h_ff<<<2 * FFD * DD / 1024, 256>>>(Wff1, Wff2, Wff_h);

    ln_split_kernel<<<ROWS, 256>>>(x, ln1_g, ln1_b, h_hi, h_lo);

    // fused QKV: N = 3072, split A (logit-critical path)
    gemm_f16<5,2><<<dim3(3 * DD / GN, ROWS / GM), 256, SM2>>>(
        h_hi, h_lo, Wqkv_h, nullptr, nullptr, qkv_hi, qkv_lo, ROWS, 3 * DD, DD);

    attn_tc<<<dim3(TT / 128, BB * HH), 256, ASMEM>>>(
        qkv_hi, qkv_lo, qkv_hi + SEG, qkv_lo + SEG, qkv_hi + 2 * SEG, att_hi);

    gemm_f16<1,1><<<dim3(DD / GN, ROWS / GM), 256, SM1>>>(
        att_hi, nullptr, Wo_h, out, x, nullptr, nullptr, ROWS, DD, DD);

    ln_split_kernel<<<ROWS, 256>>>(out, ln2_g, ln2_b, h_hi, h_lo);

    gemm_f16<2,1><<<dim3(FFD / GN, ROWS / GM), 256, SM1>>>(
        h_hi, nullptr, Wf1_h, nullptr, nullptr, ff_hi, nullptr, ROWS, FFD, DD);

    gemm_f16<3,1><<<dim3(DD / GN, ROWS / GM), 256, SM1>>>(
        ff_hi, nullptr, Wf2_h, out, nullptr, nullptr, nullptr, ROWS, DD, FFD);
}